// round 6
// baseline (speedup 1.0000x reference)
#include <cuda_runtime.h>
#include <stdint.h>

#define D 128
#define MAXN 50048
#define MAXE 600064
#define BN_EPS 1e-5f
#define CHUNK 512
#define MAXCHUNKS 128

// ---------------- scratch (no allocation allowed) ----------------
__device__ float g_h  [(size_t)MAXN * D];   // x@W_mlp (raw, pre-BN)
__device__ float g_hc [(size_t)MAXN * D];   // relu(bn1(h)) @ W_conv
__device__ float g_acc[(size_t)MAXN * D];   // GCN aggregation result
__device__ int   g_degi[MAXN];              // in-degree (real edges only)
__device__ float g_dinv[MAXN];
__device__ int   g_coff[MAXN + 1];          // CSR offsets (by dst)
__device__ int   g_cursor[MAXN];            // fill cursors
__device__ int   g_csr[MAXE];               // src indices grouped by dst
__device__ int   g_part[MAXCHUNKS];
__device__ int   g_pbase[MAXCHUNKS];
__device__ float g_sum1[D], g_sq1[D], g_sum2[D], g_sq2[D];
__device__ float g_a1[D], g_c1[D], g_a2[D], g_c2[D];

// ---------------- tf32 helpers ----------------
__device__ __forceinline__ void split_tf32(float v, uint32_t& hi, uint32_t& lo) {
    uint32_t h;
    asm("cvt.rna.tf32.f32 %0, %1;" : "=r"(h) : "f"(v));
    float l = v - __uint_as_float(h);
    uint32_t lw;
    asm("cvt.rna.tf32.f32 %0, %1;" : "=r"(lw) : "f"(l));
    hi = h; lo = lw;
}

__device__ __forceinline__ void mma_tf32(float* c, const uint32_t* a,
                                         uint32_t b0, uint32_t b1) {
    asm volatile(
        "mma.sync.aligned.m16n8k8.row.col.f32.tf32.tf32.f32 "
        "{%0,%1,%2,%3}, {%4,%5,%6,%7}, {%8,%9}, {%0,%1,%2,%3};"
        : "+f"(c[0]), "+f"(c[1]), "+f"(c[2]), "+f"(c[3])
        : "r"(a[0]), "r"(a[1]), "r"(a[2]), "r"(a[3]), "r"(b0), "r"(b1));
}

// ---------------- init ----------------
__global__ void k_init(int N) {
    int i = blockIdx.x * blockDim.x + threadIdx.x;
    if (i < D) { g_sum1[i] = 0.f; g_sq1[i] = 0.f; g_sum2[i] = 0.f; g_sq2[i] = 0.f; }
    if (i < N) g_degi[i] = 0;
}

// ---------------- degree histogram ----------------
__global__ void k_deg(const int* __restrict__ dst, int E, int N) {
    int e = blockIdx.x * blockDim.x + threadIdx.x;
    if (e < E) {
        int d = dst[e];
        if ((unsigned)d < (unsigned)N) atomicAdd(&g_degi[d], 1);
    }
}

// ---------------- hierarchical scan ----------------
__global__ void k_scan1(int N) {
    __shared__ int red[CHUNK];
    int tid = threadIdx.x;
    int i = blockIdx.x * CHUNK + tid;
    red[tid] = (i < N) ? g_degi[i] : 0;
    __syncthreads();
    #pragma unroll
    for (int off = CHUNK / 2; off > 0; off >>= 1) {
        if (tid < off) red[tid] += red[tid + off];
        __syncthreads();
    }
    if (tid == 0) g_part[blockIdx.x] = red[0];
}

__global__ void k_scan2(int nchunks) {
    __shared__ int s[MAXCHUNKS];
    int tid = threadIdx.x;  // 128 threads
    s[tid] = (tid < nchunks) ? g_part[tid] : 0;
    __syncthreads();
    #pragma unroll
    for (int off = 1; off < MAXCHUNKS; off <<= 1) {
        int v = s[tid];
        int u = (tid >= off) ? s[tid - off] : 0;
        __syncthreads();
        s[tid] = v + u;
        __syncthreads();
    }
    if (tid < nchunks) g_pbase[tid] = (tid > 0) ? s[tid - 1] : 0;
}

__global__ void k_scan3(int N) {
    __shared__ int s[CHUNK];
    int tid = threadIdx.x;
    int i = blockIdx.x * CHUNK + tid;
    int deg = (i < N) ? g_degi[i] : 0;
    s[tid] = deg;
    __syncthreads();
    #pragma unroll
    for (int off = 1; off < CHUNK; off <<= 1) {
        int v = s[tid];
        int u = (tid >= off) ? s[tid - off] : 0;
        __syncthreads();
        s[tid] = v + u;
        __syncthreads();
    }
    if (i < N) {
        int base = g_pbase[blockIdx.x];
        int excl = base + s[tid] - deg;
        g_coff[i] = excl;
        g_cursor[i] = excl;
        g_dinv[i] = rsqrtf((float)deg + 1.0f);   // +1 self loop
        if (i == N - 1) g_coff[N] = excl + deg;
    }
}

// ---------------- CSR fill ----------------
__global__ void k_fill(const int* __restrict__ src,
                       const int* __restrict__ dst, int E, int N) {
    int e = blockIdx.x * blockDim.x + threadIdx.x;
    if (e < E) {
        int d = dst[e], s = src[e];
        if ((unsigned)d < (unsigned)N && (unsigned)s < (unsigned)N) {
            int pos = atomicAdd(&g_cursor[d], 1);
            g_csr[pos] = s;
        }
    }
}

// ---------------- tf32 MMA GEMM (3xTF32), 2D warp tiling --------------------
// Block 256 thr = 8 warps as 4(M) x 2(N); warp tile 32 x 64; block 128 x 128.
// MODE 0: A=x, C=g_h, fused per-column sum/sumsq into g_sum1/g_sq1.
// MODE 1: A=g_h with fused BN1 affine + ReLU, C=g_hc, no stats.
#define AST 20   // A smem stride (uint32) — conflict-free fragment LDS
#define BST 136  // B smem stride (uint32)
template <int MODE>
__global__ void __launch_bounds__(256) k_gemm(const float* __restrict__ Ain,
                                              const float* __restrict__ B, int M) {
    __shared__ uint32_t Ah[128 * AST], Al[128 * AST];
    __shared__ uint32_t Bh[16 * BST],  Bl[16 * BST];
    const float* A = (MODE == 0) ? Ain : g_h;
    float*       C = (MODE == 0) ? g_h : g_hc;

    const int tid  = threadIdx.x;
    const int w    = tid >> 5;
    const int wm   = w >> 1;          // 0..3  (M direction, 32 rows)
    const int wn   = w & 1;           // 0..1  (N direction, 64 cols)
    const int lane = tid & 31;
    const int g    = lane >> 2;       // 0..7
    const int t    = lane & 3;        // 0..3
    const int row0 = blockIdx.x * 128;

    float acc[2][8][4];
    #pragma unroll
    for (int m = 0; m < 2; m++)
        #pragma unroll
        for (int n = 0; n < 8; n++)
            #pragma unroll
            for (int i = 0; i < 4; i++) acc[m][n][i] = 0.f;

    for (int kk = 0; kk < D; kk += 16) {
        // ---- stage A chunk [128][16] hi/lo ----
        #pragma unroll
        for (int i = 0; i < 2; i++) {
            int idx = tid + i * 256;       // float4 idx over 128x4 grid
            int r = idx >> 2;
            int c4 = idx & 3;
            float4 v = make_float4(0.f, 0.f, 0.f, 0.f);
            if (row0 + r < M)
                v = *(const float4*)(A + (size_t)(row0 + r) * D + kk + c4 * 4);
            if (MODE == 1) {
                int c = kk + c4 * 4;
                v.x = fmaxf(fmaf(v.x, g_a1[c + 0], g_c1[c + 0]), 0.f);
                v.y = fmaxf(fmaf(v.y, g_a1[c + 1], g_c1[c + 1]), 0.f);
                v.z = fmaxf(fmaf(v.z, g_a1[c + 2], g_c1[c + 2]), 0.f);
                v.w = fmaxf(fmaf(v.w, g_a1[c + 3], g_c1[c + 3]), 0.f);
            }
            uint32_t hx, lx, hy, ly, hz, lz, hw, lw;
            split_tf32(v.x, hx, lx); split_tf32(v.y, hy, ly);
            split_tf32(v.z, hz, lz); split_tf32(v.w, hw, lw);
            uint32_t* ph = &Ah[r * AST + c4 * 4];
            uint32_t* pl = &Al[r * AST + c4 * 4];
            ph[0] = hx; ph[1] = hy; ph[2] = hz; ph[3] = hw;
            pl[0] = lx; pl[1] = ly; pl[2] = lz; pl[3] = lw;
        }
        // ---- stage B chunk [16][128] hi/lo ----
        #pragma unroll
        for (int i = 0; i < 2; i++) {
            int idx = tid + i * 256;       // float4 idx over 16x32 grid
            int r = idx >> 5;
            int c4 = idx & 31;
            float4 v = *(const float4*)(B + (size_t)(kk + r) * D + c4 * 4);
            uint32_t hx, lx, hy, ly, hz, lz, hw, lw;
            split_tf32(v.x, hx, lx); split_tf32(v.y, hy, ly);
            split_tf32(v.z, hz, lz); split_tf32(v.w, hw, lw);
            uint32_t* ph = &Bh[r * BST + c4 * 4];
            uint32_t* pl = &Bl[r * BST + c4 * 4];
            ph[0] = hx; ph[1] = hy; ph[2] = hz; ph[3] = hw;
            pl[0] = lx; pl[1] = ly; pl[2] = lz; pl[3] = lw;
        }
        __syncthreads();

        #pragma unroll
        for (int ks = 0; ks < 16; ks += 8) {
            uint32_t ah[2][4], al[2][4];
            #pragma unroll
            for (int m = 0; m < 2; m++) {
                int base = wm * 32 + m * 16;
                int r0 = (base + g) * AST + ks + t;
                int r8 = (base + g + 8) * AST + ks + t;
                ah[m][0] = Ah[r0];     ah[m][1] = Ah[r8];
                ah[m][2] = Ah[r0 + 4]; ah[m][3] = Ah[r8 + 4];
                al[m][0] = Al[r0];     al[m][1] = Al[r8];
                al[m][2] = Al[r0 + 4]; al[m][3] = Al[r8 + 4];
            }
            #pragma unroll
            for (int nt = 0; nt < 8; nt++) {
                int bi = (ks + t) * BST + wn * 64 + nt * 8 + g;
                uint32_t bh0 = Bh[bi], bh1 = Bh[bi + 4 * BST];
                uint32_t bl0 = Bl[bi], bl1 = Bl[bi + 4 * BST];
                #pragma unroll
                for (int m = 0; m < 2; m++) {
                    mma_tf32(acc[m][nt], ah[m], bh0, bh1);   // hi*hi
                    mma_tf32(acc[m][nt], ah[m], bl0, bl1);   // hi*lo
                    mma_tf32(acc[m][nt], al[m], bh0, bh1);   // lo*hi
                }
            }
        }
        __syncthreads();
    }

    // ---- store tile ----
    #pragma unroll
    for (int m = 0; m < 2; m++) {
        int rA = row0 + wm * 32 + m * 16 + g;
        int rB = rA + 8;
        #pragma unroll
        for (int nt = 0; nt < 8; nt++) {
            int col = wn * 64 + nt * 8 + 2 * t;
            if (rA < M)
                *(float2*)(C + (size_t)rA * D + col) =
                    make_float2(acc[m][nt][0], acc[m][nt][1]);
            if (rB < M)
                *(float2*)(C + (size_t)rB * D + col) =
                    make_float2(acc[m][nt][2], acc[m][nt][3]);
        }
    }

    // ---- fused column stats (MODE 0): padded rows contribute exact zeros ----
    if (MODE == 0) {
        #pragma unroll
        for (int nt = 0; nt < 8; nt++) {
            #pragma unroll
            for (int j = 0; j < 2; j++) {
                float s = acc[0][nt][j] + acc[0][nt][j + 2]
                        + acc[1][nt][j] + acc[1][nt][j + 2];
                float q = acc[0][nt][j] * acc[0][nt][j]
                        + acc[0][nt][j + 2] * acc[0][nt][j + 2]
                        + acc[1][nt][j] * acc[1][nt][j]
                        + acc[1][nt][j + 2] * acc[1][nt][j + 2];
                #pragma unroll
                for (int off = 4; off < 32; off <<= 1) {
                    s += __shfl_xor_sync(0xffffffffu, s, off);
                    q += __shfl_xor_sync(0xffffffffu, q, off);
                }
                if (lane < 4) {
                    int col = wn * 64 + nt * 8 + 2 * t + j;
                    atomicAdd(&g_sum1[col], s);
                    atomicAdd(&g_sq1[col], q);
                }
            }
        }
    }
}

// ---------------- BN affine precompute: y = x*a + c ----------------
__global__ void k_affine(const float* __restrict__ gamma,
                         const float* __restrict__ beta,
                         float invN, int which) {
    int j = threadIdx.x;
    const float* sum = (which == 0) ? g_sum1 : g_sum2;
    const float* sq  = (which == 0) ? g_sq1  : g_sq2;
    float* a = (which == 0) ? g_a1 : g_a2;
    float* c = (which == 0) ? g_c1 : g_c2;
    float mean = sum[j] * invN;
    float var  = sq[j] * invN - mean * mean;
    float s = gamma[j] * rsqrtf(var + BN_EPS);
    a[j] = s;
    c[j] = beta[j] - mean * s;
}

// ---------------- gather aggregation + fused colstats2 ----------------------
__global__ void k_gather(int N) {
    __shared__ float ssum[D], ssq[D];
    int tid = threadIdx.x;
    if (tid < D) { ssum[tid] = 0.f; ssq[tid] = 0.f; }
    __syncthreads();

    int w = (blockIdx.x * blockDim.x + tid) >> 5;
    int lane = tid & 31;
    float4 acc = make_float4(0.f, 0.f, 0.f, 0.f);

    if (w < N) {
        int d = w;
        int beg = g_coff[d], end = g_coff[d + 1];
        float wd = g_dinv[d];

        // self loop
        float4 v = ((const float4*)(g_hc + (size_t)d * D))[lane];
        float w0 = wd * wd;
        acc = make_float4(w0 * v.x, w0 * v.y, w0 * v.z, w0 * v.w);

        for (int j = beg; j < end; j += 32) {
            int myidx = 0;
            float myw = 0.f;
            if (j + lane < end) {
                myidx = g_csr[j + lane];
                myw = g_dinv[myidx] * wd;
            }
            int cnt = min(32, end - j);
            for (int t = 0; t < cnt; t++) {
                int s    = __shfl_sync(0xffffffffu, myidx, t);
                float ww = __shfl_sync(0xffffffffu, myw, t);
                float4 u = ((const float4*)(g_hc + (size_t)s * D))[lane];
                acc.x = fmaf(ww, u.x, acc.x);
                acc.y = fmaf(ww, u.y, acc.y);
                acc.z = fmaf(ww, u.z, acc.z);
                acc.w = fmaf(ww, u.w, acc.w);
            }
        }
        ((float4*)(g_acc + (size_t)d * D))[lane] = acc;
    }

    // fused BN2 stats
    int c = lane * 4;
    atomicAdd(&ssum[c + 0], acc.x); atomicAdd(&ssq[c + 0], acc.x * acc.x);
    atomicAdd(&ssum[c + 1], acc.y); atomicAdd(&ssq[c + 1], acc.y * acc.y);
    atomicAdd(&ssum[c + 2], acc.z); atomicAdd(&ssq[c + 2], acc.z * acc.z);
    atomicAdd(&ssum[c + 3], acc.w); atomicAdd(&ssq[c + 3], acc.w * acc.w);
    __syncthreads();
    if (tid < D) {
        atomicAdd(&g_sum2[tid], ssum[tid]);
        atomicAdd(&g_sq2[tid], ssq[tid]);
    }
}

// ---------------- finalize: BN2 affine + relu ----------------
__global__ void k_final(float* __restrict__ out, int N) {
    int t = blockIdx.x * blockDim.x + threadIdx.x;
    int r = t >> 5, lane = t & 31;
    if (r >= N) return;
    float4 v = ((const float4*)(g_acc + (size_t)r * D))[lane];
    int c = lane * 4;
    v.x = fmaxf(fmaf(v.x, g_a2[c + 0], g_c2[c + 0]), 0.f);
    v.y = fmaxf(fmaf(v.y, g_a2[c + 1], g_c2[c + 1]), 0.f);
    v.z = fmaxf(fmaf(v.z, g_a2[c + 2], g_c2[c + 2]), 0.f);
    v.w = fmaxf(fmaf(v.w, g_a2[c + 3], g_c2[c + 3]), 0.f);
    ((float4*)(out + (size_t)r * D))[lane] = v;
}

// ---------------- launch ----------------
extern "C" void kernel_launch(void* const* d_in, const int* in_sizes, int n_in,
                              void* d_out, int out_size) {
    const float* x    = (const float*)d_in[0];
    const int*   ei   = (const int*)d_in[1];   // int64 in reference -> delivered int32
    const float* Wm   = (const float*)d_in[2];
    // d_in[3] = b_mlp  : cancels inside training-mode BatchNorm
    const float* gam1 = (const float*)d_in[4];
    const float* bet1 = (const float*)d_in[5];
    const float* Wc   = (const float*)d_in[6];
    // d_in[7] = b_conv : cancels inside training-mode BatchNorm
    const float* gam2 = (const float*)d_in[8];
    const float* bet2 = (const float*)d_in[9];
    float* out = (float*)d_out;

    const int N = in_sizes[0] / D;
    const int E = in_sizes[1] / 2;
    const int* srcp = ei;
    const int* dstp = ei + E;
    const float invN = 1.0f / (float)N;
    const int nchunks = (N + CHUNK - 1) / CHUNK;

    k_init<<<(N + 255) / 256, 256>>>(N);
    k_gemm<0><<<(N + 127) / 128, 256>>>(x, Wm, N);
    k_affine<<<1, 128>>>(gam1, bet1, invN, 0);
    k_gemm<1><<<(N + 127) / 128, 256>>>(nullptr, Wc, N);   // 4th: ncu sample slot
    k_deg<<<(E + 255) / 256, 256>>>(dstp, E, N);
    k_scan1<<<nchunks, CHUNK>>>(N);
    k_scan2<<<1, MAXCHUNKS>>>(nchunks);
    k_scan3<<<nchunks, CHUNK>>>(N);
    k_fill<<<(E + 255) / 256, 256>>>(srcp, dstp, E, N);
    k_gather<<<(N * 32 + 255) / 256, 256>>>(N);
    k_affine<<<1, 128>>>(gam2, bet2, invN, 1);
    k_final<<<(N * 32 + 255) / 256, 256>>>(out, N);
}

// round 7
// speedup vs baseline: 1.5128x; 1.5128x over previous
#include <cuda_runtime.h>
#include <cuda_bf16.h>
#include <stdint.h>

#define D 128
#define MAXN 50048
#define MAXE 600064
#define BN_EPS 1e-5f
#define CHUNK 512
#define MAXCHUNKS 128

// ---------------- scratch (no allocation allowed) ----------------
__device__ float g_h  [(size_t)MAXN * D];   // x@W_mlp (raw, pre-BN)
__device__ float g_hc [(size_t)MAXN * D];   // relu(bn1(h)) @ W_conv
__device__ float g_acc[(size_t)MAXN * D];   // GCN aggregation result
__device__ int   g_degi[MAXN];
__device__ float g_dinv[MAXN];
__device__ int   g_coff[MAXN + 1];
__device__ int   g_cursor[MAXN];
__device__ int   g_csr[MAXE];
__device__ int   g_part[MAXCHUNKS];
__device__ int   g_pbase[MAXCHUNKS];
__device__ float g_sum1[D], g_sq1[D], g_sum2[D], g_sq2[D];
__device__ float g_a1[D], g_c1[D], g_a2[D], g_c2[D];

// ---------------- bf16 split helpers ----------------
// v = hi + lo with hi, lo bf16; dropped term lo_a*lo_b ~ 2^-16 relative.
__device__ __forceinline__ void split_bf16(float v, float& hi, float& lo) {
    __nv_bfloat16 h = __float2bfloat16_rn(v);
    hi = __bfloat162float(h);
    lo = v - hi;
}
__device__ __forceinline__ uint32_t pack_bf16x2(float a, float b) {
    __nv_bfloat162 p = __floats2bfloat162_rn(a, b);   // a -> low half, b -> high
    return *reinterpret_cast<uint32_t*>(&p);
}

__device__ __forceinline__ void mma_bf16(float* c, const uint32_t* a,
                                         uint32_t b0, uint32_t b1) {
    asm volatile(
        "mma.sync.aligned.m16n8k16.row.col.f32.bf16.bf16.f32 "
        "{%0,%1,%2,%3}, {%4,%5,%6,%7}, {%8,%9}, {%0,%1,%2,%3};"
        : "+f"(c[0]), "+f"(c[1]), "+f"(c[2]), "+f"(c[3])
        : "r"(a[0]), "r"(a[1]), "r"(a[2]), "r"(a[3]), "r"(b0), "r"(b1));
}

// ---------------- init ----------------
__global__ void k_init(int N) {
    int i = blockIdx.x * blockDim.x + threadIdx.x;
    if (i < D) { g_sum1[i] = 0.f; g_sq1[i] = 0.f; g_sum2[i] = 0.f; g_sq2[i] = 0.f; }
    if (i < N) g_degi[i] = 0;
}

// ---------------- degree histogram ----------------
__global__ void k_deg(const int* __restrict__ dst, int E, int N) {
    int e = blockIdx.x * blockDim.x + threadIdx.x;
    if (e < E) {
        int d = dst[e];
        if ((unsigned)d < (unsigned)N) atomicAdd(&g_degi[d], 1);
    }
}

// ---------------- hierarchical scan ----------------
__global__ void k_scan1(int N) {
    __shared__ int red[CHUNK];
    int tid = threadIdx.x;
    int i = blockIdx.x * CHUNK + tid;
    red[tid] = (i < N) ? g_degi[i] : 0;
    __syncthreads();
    #pragma unroll
    for (int off = CHUNK / 2; off > 0; off >>= 1) {
        if (tid < off) red[tid] += red[tid + off];
        __syncthreads();
    }
    if (tid == 0) g_part[blockIdx.x] = red[0];
}

__global__ void k_scan2(int nchunks) {
    __shared__ int s[MAXCHUNKS];
    int tid = threadIdx.x;  // 128 threads
    s[tid] = (tid < nchunks) ? g_part[tid] : 0;
    __syncthreads();
    #pragma unroll
    for (int off = 1; off < MAXCHUNKS; off <<= 1) {
        int v = s[tid];
        int u = (tid >= off) ? s[tid - off] : 0;
        __syncthreads();
        s[tid] = v + u;
        __syncthreads();
    }
    if (tid < nchunks) g_pbase[tid] = (tid > 0) ? s[tid - 1] : 0;
}

__global__ void k_scan3(int N) {
    __shared__ int s[CHUNK];
    int tid = threadIdx.x;
    int i = blockIdx.x * CHUNK + tid;
    int deg = (i < N) ? g_degi[i] : 0;
    s[tid] = deg;
    __syncthreads();
    #pragma unroll
    for (int off = 1; off < CHUNK; off <<= 1) {
        int v = s[tid];
        int u = (tid >= off) ? s[tid - off] : 0;
        __syncthreads();
        s[tid] = v + u;
        __syncthreads();
    }
    if (i < N) {
        int base = g_pbase[blockIdx.x];
        int excl = base + s[tid] - deg;
        g_coff[i] = excl;
        g_cursor[i] = excl;
        g_dinv[i] = rsqrtf((float)deg + 1.0f);   // +1 self loop
        if (i == N - 1) g_coff[N] = excl + deg;
    }
}

// ---------------- CSR fill ----------------
__global__ void k_fill(const int* __restrict__ src,
                       const int* __restrict__ dst, int E, int N) {
    int e = blockIdx.x * blockDim.x + threadIdx.x;
    if (e < E) {
        int d = dst[e], s = src[e];
        if ((unsigned)d < (unsigned)N && (unsigned)s < (unsigned)N) {
            int pos = atomicAdd(&g_cursor[d], 1);
            g_csr[pos] = s;
        }
    }
}

// ---------------- bf16x3 MMA GEMM: C[M,128] = act(A[M,128]) @ B[128,128] ----
// m16n8k16 bf16 MMA, hi/lo split (error ~2^-16). 1D warp layout (R5-proven):
// 8 warps x 16 rows, each warp covers all 128 cols. k-chunk = 16.
// MODE 0: A=x, C=g_h.  MODE 1: A=g_h + BN1 affine + ReLU, C=g_hc.
#define APST 12   // A packed smem stride (uint32 words per row; 8 used)
#define BPST 136  // B packed smem stride (uint32 words per pair-row; 128 used)
template <int MODE>
__global__ void __launch_bounds__(256, 2) k_gemm(const float* __restrict__ Ain,
                                                 const float* __restrict__ B, int M) {
    __shared__ uint32_t Ahp[128 * APST], Alp[128 * APST];
    __shared__ uint32_t Bhp[8 * BPST],   Blp[8 * BPST];
    const float* A = (MODE == 0) ? Ain : g_h;
    float*       C = (MODE == 0) ? g_h : g_hc;

    const int tid  = threadIdx.x;
    const int w    = tid >> 5;        // warp id 0..7: rows w*16..w*16+15
    const int lane = tid & 31;
    const int g    = lane >> 2;       // 0..7
    const int t    = lane & 3;        // 0..3
    const int row0 = blockIdx.x * 128;

    float acc[16][4];
    #pragma unroll
    for (int n = 0; n < 16; n++)
        #pragma unroll
        for (int i = 0; i < 4; i++) acc[n][i] = 0.f;

    for (int kk = 0; kk < D; kk += 16) {
        // ---- stage A chunk [128 rows][16 k] as bf16 pairs along k ----
        #pragma unroll
        for (int i = 0; i < 2; i++) {
            int idx = tid + i * 256;          // 512 float4 units (128x4)
            int r = idx >> 2;
            int c4 = idx & 3;                 // k-subgroup: words 2*c4, 2*c4+1
            float4 v = make_float4(0.f, 0.f, 0.f, 0.f);
            if (row0 + r < M)
                v = *(const float4*)(A + (size_t)(row0 + r) * D + kk + c4 * 4);
            if (MODE == 1) {
                int c = kk + c4 * 4;
                v.x = fmaxf(fmaf(v.x, g_a1[c + 0], g_c1[c + 0]), 0.f);
                v.y = fmaxf(fmaf(v.y, g_a1[c + 1], g_c1[c + 1]), 0.f);
                v.z = fmaxf(fmaf(v.z, g_a1[c + 2], g_c1[c + 2]), 0.f);
                v.w = fmaxf(fmaf(v.w, g_a1[c + 3], g_c1[c + 3]), 0.f);
            }
            float hx, lx, hy, ly, hz, lz, hw, lw;
            split_bf16(v.x, hx, lx); split_bf16(v.y, hy, ly);
            split_bf16(v.z, hz, lz); split_bf16(v.w, hw, lw);
            uint32_t* ph = &Ahp[r * APST + c4 * 2];
            uint32_t* pl = &Alp[r * APST + c4 * 2];
            ph[0] = pack_bf16x2(hx, hy); ph[1] = pack_bf16x2(hz, hw);
            pl[0] = pack_bf16x2(lx, ly); pl[1] = pack_bf16x2(lz, lw);
        }
        // ---- stage B chunk [16 k][128 n] as bf16 pairs along k ----
        {
            int k2 = tid >> 5;                 // pair-row 0..7
            int c4 = tid & 31;                 // col group (4 cols)
            float4 v0 = *(const float4*)(B + (size_t)(kk + 2 * k2) * D + c4 * 4);
            float4 v1 = *(const float4*)(B + (size_t)(kk + 2 * k2 + 1) * D + c4 * 4);
            float h0x, l0x, h0y, l0y, h0z, l0z, h0w, l0w;
            float h1x, l1x, h1y, l1y, h1z, l1z, h1w, l1w;
            split_bf16(v0.x, h0x, l0x); split_bf16(v0.y, h0y, l0y);
            split_bf16(v0.z, h0z, l0z); split_bf16(v0.w, h0w, l0w);
            split_bf16(v1.x, h1x, l1x); split_bf16(v1.y, h1y, l1y);
            split_bf16(v1.z, h1z, l1z); split_bf16(v1.w, h1w, l1w);
            uint32_t* ph = &Bhp[k2 * BPST + c4 * 4];
            uint32_t* pl = &Blp[k2 * BPST + c4 * 4];
            ph[0] = pack_bf16x2(h0x, h1x); ph[1] = pack_bf16x2(h0y, h1y);
            ph[2] = pack_bf16x2(h0z, h1z); ph[3] = pack_bf16x2(h0w, h1w);
            pl[0] = pack_bf16x2(l0x, l1x); pl[1] = pack_bf16x2(l0y, l1y);
            pl[2] = pack_bf16x2(l0z, l1z); pl[3] = pack_bf16x2(l0w, l1w);
        }
        __syncthreads();

        // ---- one m16n8k16 step covers the whole 16-k chunk ----
        uint32_t ah[4], al[4];
        {
            int r0 = (w * 16 + g) * APST + t;
            int r8 = (w * 16 + g + 8) * APST + t;
            ah[0] = Ahp[r0];     ah[1] = Ahp[r8];
            ah[2] = Ahp[r0 + 4]; ah[3] = Ahp[r8 + 4];
            al[0] = Alp[r0];     al[1] = Alp[r8];
            al[2] = Alp[r0 + 4]; al[3] = Alp[r8 + 4];
        }
        #pragma unroll
        for (int nt = 0; nt < 16; nt++) {
            int bi = t * BPST + nt * 8 + g;
            uint32_t bh0 = Bhp[bi], bh1 = Bhp[bi + 4 * BPST];
            uint32_t bl0 = Blp[bi], bl1 = Blp[bi + 4 * BPST];
            mma_bf16(acc[nt], ah, bh0, bh1);   // hi*hi
            mma_bf16(acc[nt], ah, bl0, bl1);   // hi*lo
            mma_bf16(acc[nt], al, bh0, bh1);   // lo*hi
        }
        __syncthreads();
    }

    // ---- store: c0/c1 -> (row, 2t), c2/c3 -> (row+8, 2t) ----
    int rA = row0 + w * 16 + g;
    int rB = rA + 8;
    #pragma unroll
    for (int nt = 0; nt < 16; nt++) {
        int col = nt * 8 + 2 * t;
        if (rA < M)
            *(float2*)(C + (size_t)rA * D + col) = make_float2(acc[nt][0], acc[nt][1]);
        if (rB < M)
            *(float2*)(C + (size_t)rB * D + col) = make_float2(acc[nt][2], acc[nt][3]);
    }
}

// ---------------- per-column sum / sumsq (float4 + cross-warp reduce) -------
__global__ void k_colstats(int M, int which) {
    const float* X = (which == 0) ? g_h : g_acc;
    float* sum = (which == 0) ? g_sum1 : g_sum2;
    float* sq  = (which == 0) ? g_sq1  : g_sq2;
    __shared__ float ss[8][D], sr[8][D];
    int tid = threadIdx.x;
    int wid = tid >> 5, lane = tid & 31;
    float4 s = make_float4(0.f, 0.f, 0.f, 0.f);
    float4 q = make_float4(0.f, 0.f, 0.f, 0.f);
    for (int r = blockIdx.x * 8 + wid; r < M; r += gridDim.x * 8) {
        float4 v = ((const float4*)(X + (size_t)r * D))[lane];
        s.x += v.x; s.y += v.y; s.z += v.z; s.w += v.w;
        q.x += v.x * v.x; q.y += v.y * v.y; q.z += v.z * v.z; q.w += v.w * v.w;
    }
    ((float4*)ss[wid])[lane] = s;
    ((float4*)sr[wid])[lane] = q;
    __syncthreads();
    if (tid < D) {
        float a = 0.f, b = 0.f;
        #pragma unroll
        for (int wv = 0; wv < 8; wv++) { a += ss[wv][tid]; b += sr[wv][tid]; }
        atomicAdd(&sum[tid], a);
        atomicAdd(&sq[tid], b);
    }
}

// ---------------- BN affine precompute: y = x*a + c ----------------
__global__ void k_affine(const float* __restrict__ gamma,
                         const float* __restrict__ beta,
                         float invN, int which) {
    int j = threadIdx.x;
    const float* sum = (which == 0) ? g_sum1 : g_sum2;
    const float* sq  = (which == 0) ? g_sq1  : g_sq2;
    float* a = (which == 0) ? g_a1 : g_a2;
    float* c = (which == 0) ? g_c1 : g_c2;
    float mean = sum[j] * invN;
    float var  = sq[j] * invN - mean * mean;
    float s = gamma[j] * rsqrtf(var + BN_EPS);
    a[j] = s;
    c[j] = beta[j] - mean * s;
}

// ---------------- gather aggregation: one warp per destination node ---------
__global__ void k_gather(int N) {
    int w = (blockIdx.x * blockDim.x + threadIdx.x) >> 5;
    int lane = threadIdx.x & 31;
    if (w >= N) return;
    int d = w;
    int beg = g_coff[d], end = g_coff[d + 1];
    float wd = g_dinv[d];

    // self loop
    float4 v = ((const float4*)(g_hc + (size_t)d * D))[lane];
    float w0 = wd * wd;
    float4 acc = make_float4(w0 * v.x, w0 * v.y, w0 * v.z, w0 * v.w);

    for (int j = beg; j < end; j += 32) {
        int myidx = 0;
        float myw = 0.f;
        if (j + lane < end) {
            myidx = g_csr[j + lane];
            myw = g_dinv[myidx] * wd;
        }
        int cnt = min(32, end - j);
        for (int t = 0; t < cnt; t++) {
            int s    = __shfl_sync(0xffffffffu, myidx, t);
            float ww = __shfl_sync(0xffffffffu, myw, t);
            float4 u = ((const float4*)(g_hc + (size_t)s * D))[lane];
            acc.x = fmaf(ww, u.x, acc.x);
            acc.y = fmaf(ww, u.y, acc.y);
            acc.z = fmaf(ww, u.z, acc.z);
            acc.w = fmaf(ww, u.w, acc.w);
        }
    }
    ((float4*)(g_acc + (size_t)d * D))[lane] = acc;
}

// ---------------- finalize: BN2 affine + relu ----------------
__global__ void k_final(float* __restrict__ out, int N) {
    int t = blockIdx.x * blockDim.x + threadIdx.x;
    int r = t >> 5, lane = t & 31;
    if (r >= N) return;
    float4 v = ((const float4*)(g_acc + (size_t)r * D))[lane];
    int c = lane * 4;
    v.x = fmaxf(fmaf(v.x, g_a2[c + 0], g_c2[c + 0]), 0.f);
    v.y = fmaxf(fmaf(v.y, g_a2[c + 1], g_c2[c + 1]), 0.f);
    v.z = fmaxf(fmaf(v.z, g_a2[c + 2], g_c2[c + 2]), 0.f);
    v.w = fmaxf(fmaf(v.w, g_a2[c + 3], g_c2[c + 3]), 0.f);
    ((float4*)(out + (size_t)r * D))[lane] = v;
}

// ---------------- launch ----------------
extern "C" void kernel_launch(void* const* d_in, const int* in_sizes, int n_in,
                              void* d_out, int out_size) {
    const float* x    = (const float*)d_in[0];
    const int*   ei   = (const int*)d_in[1];   // int64 in reference -> delivered int32
    const float* Wm   = (const float*)d_in[2];
    // d_in[3] = b_mlp  : cancels inside training-mode BatchNorm
    const float* gam1 = (const float*)d_in[4];
    const float* bet1 = (const float*)d_in[5];
    const float* Wc   = (const float*)d_in[6];
    // d_in[7] = b_conv : cancels inside training-mode BatchNorm
    const float* gam2 = (const float*)d_in[8];
    const float* bet2 = (const float*)d_in[9];
    float* out = (float*)d_out;

    const int N = in_sizes[0] / D;
    const int E = in_sizes[1] / 2;
    const int* srcp = ei;
    const int* dstp = ei + E;
    const float invN = 1.0f / (float)N;
    const int nchunks = (N + CHUNK - 1) / CHUNK;

    k_init<<<(N + 255) / 256, 256>>>(N);
    k_deg<<<(E + 255) / 256, 256>>>(dstp, E, N);
    k_scan1<<<nchunks, CHUNK>>>(N);
    k_gemm<0><<<(N + 127) / 128, 256>>>(x, Wm, N);   // 4th: ncu sample slot
    k_scan2<<<1, MAXCHUNKS>>>(nchunks);
    k_scan3<<<nchunks, CHUNK>>>(N);
    k_fill<<<(E + 255) / 256, 256>>>(srcp, dstp, E, N);
    k_colstats<<<256, 256>>>(N, 0);
    k_affine<<<1, 128>>>(gam1, bet1, invN, 0);
    k_gemm<1><<<(N + 127) / 128, 256>>>(nullptr, Wc, N);
    k_gather<<<(N * 32 + 255) / 256, 256>>>(N);
    k_colstats<<<256, 256>>>(N, 1);
    k_affine<<<1, 128>>>(gam2, bet2, invN, 1);
    k_final<<<(N * 32 + 255) / 256, 256>>>(out, N);
}

// round 8
// speedup vs baseline: 1.5847x; 1.0475x over previous
#include <cuda_runtime.h>
#include <cuda_bf16.h>
#include <stdint.h>

#define D 128
#define MAXN 50048
#define MAXE 600064
#define BN_EPS 1e-5f
#define CHUNK 512
#define MAXCHUNKS 128

// ---------------- scratch (no allocation allowed) ----------------
__device__ float g_h  [(size_t)MAXN * D];   // x@W_mlp (raw, pre-BN)
__device__ float g_hc [(size_t)MAXN * D];   // relu(bn1(h)) @ W_conv
__device__ float g_acc[(size_t)MAXN * D];   // GCN aggregation result
__device__ int   g_degi[MAXN];
__device__ float g_dinv[MAXN];
__device__ int   g_coff[MAXN + 1];
__device__ int   g_cursor[MAXN];
__device__ int   g_csr[MAXE];
__device__ int   g_part[MAXCHUNKS];
__device__ int   g_pbase[MAXCHUNKS];
__device__ float g_sum1[D], g_sq1[D], g_sum2[D], g_sq2[D];
__device__ float g_a1[D], g_c1[D], g_a2[D], g_c2[D];

// ---------------- bf16 split helpers ----------------
__device__ __forceinline__ void split_bf16(float v, float& hi, float& lo) {
    __nv_bfloat16 h = __float2bfloat16_rn(v);
    hi = __bfloat162float(h);
    lo = v - hi;
}
__device__ __forceinline__ uint32_t pack_bf16x2(float a, float b) {
    __nv_bfloat162 p = __floats2bfloat162_rn(a, b);
    return *reinterpret_cast<uint32_t*>(&p);
}

__device__ __forceinline__ void mma_bf16(float* c, const uint32_t* a,
                                         uint32_t b0, uint32_t b1) {
    asm volatile(
        "mma.sync.aligned.m16n8k16.row.col.f32.bf16.bf16.f32 "
        "{%0,%1,%2,%3}, {%4,%5,%6,%7}, {%8,%9}, {%0,%1,%2,%3};"
        : "+f"(c[0]), "+f"(c[1]), "+f"(c[2]), "+f"(c[3])
        : "r"(a[0]), "r"(a[1]), "r"(a[2]), "r"(a[3]), "r"(b0), "r"(b1));
}

// ---------------- degree histogram ----------------
__global__ void k_deg(const int* __restrict__ dst, int E, int N) {
    int e = blockIdx.x * blockDim.x + threadIdx.x;
    if (e < E) {
        int d = dst[e];
        if ((unsigned)d < (unsigned)N) atomicAdd(&g_degi[d], 1);
    }
}

// ---------------- hierarchical scan ----------------
__global__ void k_scan1(int N) {
    __shared__ int red[CHUNK];
    int tid = threadIdx.x;
    int i = blockIdx.x * CHUNK + tid;
    red[tid] = (i < N) ? g_degi[i] : 0;
    __syncthreads();
    #pragma unroll
    for (int off = CHUNK / 2; off > 0; off >>= 1) {
        if (tid < off) red[tid] += red[tid + off];
        __syncthreads();
    }
    if (tid == 0) g_part[blockIdx.x] = red[0];
}

// also zeroes the BN stat accumulators (runs before any colstats)
__global__ void k_scan2(int nchunks) {
    __shared__ int s[MAXCHUNKS];
    int tid = threadIdx.x;  // 128 threads
    if (tid < D) { g_sum1[tid] = 0.f; g_sq1[tid] = 0.f; g_sum2[tid] = 0.f; g_sq2[tid] = 0.f; }
    s[tid] = (tid < nchunks) ? g_part[tid] : 0;
    __syncthreads();
    #pragma unroll
    for (int off = 1; off < MAXCHUNKS; off <<= 1) {
        int v = s[tid];
        int u = (tid >= off) ? s[tid - off] : 0;
        __syncthreads();
        s[tid] = v + u;
        __syncthreads();
    }
    if (tid < nchunks) g_pbase[tid] = (tid > 0) ? s[tid - 1] : 0;
}

__global__ void k_scan3(int N) {
    __shared__ int s[CHUNK];
    int tid = threadIdx.x;
    int i = blockIdx.x * CHUNK + tid;
    int deg = (i < N) ? g_degi[i] : 0;
    s[tid] = deg;
    __syncthreads();
    #pragma unroll
    for (int off = 1; off < CHUNK; off <<= 1) {
        int v = s[tid];
        int u = (tid >= off) ? s[tid - off] : 0;
        __syncthreads();
        s[tid] = v + u;
        __syncthreads();
    }
    if (i < N) {
        int base = g_pbase[blockIdx.x];
        int excl = base + s[tid] - deg;
        g_coff[i] = excl;
        g_cursor[i] = excl;
        g_dinv[i] = rsqrtf((float)deg + 1.0f);   // +1 self loop
        if (i == N - 1) g_coff[N] = excl + deg;
    }
}

// ---------------- CSR fill ----------------
__global__ void k_fill(const int* __restrict__ src,
                       const int* __restrict__ dst, int E, int N) {
    int e = blockIdx.x * blockDim.x + threadIdx.x;
    if (e < E) {
        int d = dst[e], s = src[e];
        if ((unsigned)d < (unsigned)N && (unsigned)s < (unsigned)N) {
            int pos = atomicAdd(&g_cursor[d], 1);
            g_csr[pos] = s;
        }
    }
}

// ---------------- bf16x3 MMA GEMM, cp.async pipelined -----------------------
// C[M,128] = act(A[M,128]) @ B[128,128].  8 warps x 16 rows, k-chunk 16.
// MODE 0: A=x, C=g_h.  MODE 1: A=g_h + fused BN1 affine + ReLU, C=g_hc.
#define APST 12    // A packed smem stride (uint32 words per row; 8 used)
#define BPST 136   // B packed smem stride (uint32 words per pair-row)
#define RAWST 20   // raw A row stride in floats (80B, 16B-aligned rows)
template <int MODE>
__global__ void __launch_bounds__(256, 2) k_gemm(const float* __restrict__ Ain,
                                                 const float* __restrict__ B, int M) {
    __shared__ __align__(16) float Araw[2][128 * RAWST];
    __shared__ uint32_t Ahp[128 * APST], Alp[128 * APST];
    __shared__ uint32_t Bhp[8 * BPST],   Blp[8 * BPST];
    const float* A = (MODE == 0) ? Ain : g_h;
    float*       C = (MODE == 0) ? g_h : g_hc;

    const int tid  = threadIdx.x;
    const int w    = tid >> 5;
    const int lane = tid & 31;
    const int g    = lane >> 2;
    const int t    = lane & 3;
    const int row0 = blockIdx.x * 128;

    float acc[16][4];
    #pragma unroll
    for (int n = 0; n < 16; n++)
        #pragma unroll
        for (int i = 0; i < 4; i++) acc[n][i] = 0.f;

    // issue async copy of A chunk kk into raw buffer buf (OOB rows zero-filled)
    auto issueA = [&](int kk, int buf) {
        #pragma unroll
        for (int i = 0; i < 2; i++) {
            int idx = tid + i * 256;
            int r = idx >> 2, c4 = idx & 3;
            int gr = row0 + r;
            const float* src = A + (size_t)(gr < M ? gr : 0) * D + kk + c4 * 4;
            uint32_t dst = (uint32_t)__cvta_generic_to_shared(
                &Araw[buf][r * RAWST + c4 * 4]);
            int sz = (gr < M) ? 16 : 0;
            asm volatile("cp.async.cg.shared.global [%0], [%1], 16, %2;\n"
                         :: "r"(dst), "l"(src), "r"(sz));
        }
        asm volatile("cp.async.commit_group;\n");
    };

    // convert raw A chunk -> packed bf16 hi/lo planes (+affine/relu for MODE 1)
    auto convertA = [&](int kk, int buf) {
        #pragma unroll
        for (int i = 0; i < 2; i++) {
            int idx = tid + i * 256;
            int r = idx >> 2, c4 = idx & 3;
            float4 v = *(const float4*)&Araw[buf][r * RAWST + c4 * 4];
            if (MODE == 1) {
                int c = kk + c4 * 4;
                v.x = fmaxf(fmaf(v.x, g_a1[c + 0], g_c1[c + 0]), 0.f);
                v.y = fmaxf(fmaf(v.y, g_a1[c + 1], g_c1[c + 1]), 0.f);
                v.z = fmaxf(fmaf(v.z, g_a1[c + 2], g_c1[c + 2]), 0.f);
                v.w = fmaxf(fmaf(v.w, g_a1[c + 3], g_c1[c + 3]), 0.f);
            }
            float hx, lx, hy, ly, hz, lz, hw, lw;
            split_bf16(v.x, hx, lx); split_bf16(v.y, hy, ly);
            split_bf16(v.z, hz, lz); split_bf16(v.w, hw, lw);
            uint32_t* ph = &Ahp[r * APST + c4 * 2];
            uint32_t* pl = &Alp[r * APST + c4 * 2];
            ph[0] = pack_bf16x2(hx, hy); ph[1] = pack_bf16x2(hz, hw);
            pl[0] = pack_bf16x2(lx, ly); pl[1] = pack_bf16x2(lz, lw);
        }
    };

    // stage B chunk (small, L2-resident after first wave)
    auto stageB = [&](int kk) {
        int k2 = tid >> 5;
        int c4 = tid & 31;
        float4 v0 = *(const float4*)(B + (size_t)(kk + 2 * k2) * D + c4 * 4);
        float4 v1 = *(const float4*)(B + (size_t)(kk + 2 * k2 + 1) * D + c4 * 4);
        float h0x, l0x, h0y, l0y, h0z, l0z, h0w, l0w;
        float h1x, l1x, h1y, l1y, h1z, l1z, h1w, l1w;
        split_bf16(v0.x, h0x, l0x); split_bf16(v0.y, h0y, l0y);
        split_bf16(v0.z, h0z, l0z); split_bf16(v0.w, h0w, l0w);
        split_bf16(v1.x, h1x, l1x); split_bf16(v1.y, h1y, l1y);
        split_bf16(v1.z, h1z, l1z); split_bf16(v1.w, h1w, l1w);
        uint32_t* ph = &Bhp[k2 * BPST + c4 * 4];
        uint32_t* pl = &Blp[k2 * BPST + c4 * 4];
        ph[0] = pack_bf16x2(h0x, h1x); ph[1] = pack_bf16x2(h0y, h1y);
        ph[2] = pack_bf16x2(h0z, h1z); ph[3] = pack_bf16x2(h0w, h1w);
        pl[0] = pack_bf16x2(l0x, l1x); pl[1] = pack_bf16x2(l0y, l1y);
        pl[2] = pack_bf16x2(l0z, l1z); pl[3] = pack_bf16x2(l0w, l1w);
    };

    // ---- prolog: chunk 0 ----
    issueA(0, 0);
    asm volatile("cp.async.wait_group 0;\n");
    convertA(0, 0);
    stageB(0);
    __syncthreads();

    for (int c = 0; c < 8; c++) {
        int kk = c * 16;
        if (c < 7) issueA(kk + 16, (c + 1) & 1);   // in flight during MMAs

        uint32_t ah[4], al[4];
        {
            int r0 = (w * 16 + g) * APST + t;
            int r8 = (w * 16 + g + 8) * APST + t;
            ah[0] = Ahp[r0];     ah[1] = Ahp[r8];
            ah[2] = Ahp[r0 + 4]; ah[3] = Ahp[r8 + 4];
            al[0] = Alp[r0];     al[1] = Alp[r8];
            al[2] = Alp[r0 + 4]; al[3] = Alp[r8 + 4];
        }
        #pragma unroll
        for (int nt = 0; nt < 16; nt++) {
            int bi = t * BPST + nt * 8 + g;
            uint32_t bh0 = Bhp[bi], bh1 = Bhp[bi + 4 * BPST];
            uint32_t bl0 = Blp[bi], bl1 = Blp[bi + 4 * BPST];
            mma_bf16(acc[nt], ah, bh0, bh1);   // hi*hi
            mma_bf16(acc[nt], ah, bl0, bl1);   // hi*lo
            mma_bf16(acc[nt], al, bh0, bh1);   // lo*hi
        }
        __syncthreads();                        // packed planes fully consumed

        if (c < 7) {
            asm volatile("cp.async.wait_group 0;\n");
            convertA(kk + 16, (c + 1) & 1);
            stageB(kk + 16);
            __syncthreads();                    // packed planes ready
        }
    }

    // ---- store: c0/c1 -> (row, 2t), c2/c3 -> (row+8, 2t) ----
    int rA = row0 + w * 16 + g;
    int rB = rA + 8;
    #pragma unroll
    for (int nt = 0; nt < 16; nt++) {
        int col = nt * 8 + 2 * t;
        if (rA < M)
            *(float2*)(C + (size_t)rA * D + col) = make_float2(acc[nt][0], acc[nt][1]);
        if (rB < M)
            *(float2*)(C + (size_t)rB * D + col) = make_float2(acc[nt][2], acc[nt][3]);
    }
}

// ---------------- per-column sum / sumsq (float4 + cross-warp reduce) -------
__global__ void k_colstats(int M, int which) {
    const float* X = (which == 0) ? g_h : g_acc;
    float* sum = (which == 0) ? g_sum1 : g_sum2;
    float* sq  = (which == 0) ? g_sq1  : g_sq2;
    __shared__ float ss[8][D], sr[8][D];
    int tid = threadIdx.x;
    int wid = tid >> 5, lane = tid & 31;
    float4 s = make_float4(0.f, 0.f, 0.f, 0.f);
    float4 q = make_float4(0.f, 0.f, 0.f, 0.f);
    for (int r = blockIdx.x * 8 + wid; r < M; r += gridDim.x * 8) {
        float4 v = ((const float4*)(X + (size_t)r * D))[lane];
        s.x += v.x; s.y += v.y; s.z += v.z; s.w += v.w;
        q.x += v.x * v.x; q.y += v.y * v.y; q.z += v.z * v.z; q.w += v.w * v.w;
    }
    ((float4*)ss[wid])[lane] = s;
    ((float4*)sr[wid])[lane] = q;
    __syncthreads();
    if (tid < D) {
        float a = 0.f, b = 0.f;
        #pragma unroll
        for (int wv = 0; wv < 8; wv++) { a += ss[wv][tid]; b += sr[wv][tid]; }
        atomicAdd(&sum[tid], a);
        atomicAdd(&sq[tid], b);
    }
}

// ---------------- BN affine precompute: y = x*a + c ----------------
__global__ void k_affine(const float* __restrict__ gamma,
                         const float* __restrict__ beta,
                         float invN, int which) {
    int j = threadIdx.x;
    const float* sum = (which == 0) ? g_sum1 : g_sum2;
    const float* sq  = (which == 0) ? g_sq1  : g_sq2;
    float* a = (which == 0) ? g_a1 : g_a2;
    float* c = (which == 0) ? g_c1 : g_c2;
    float mean = sum[j] * invN;
    float var  = sq[j] * invN - mean * mean;
    float s = gamma[j] * rsqrtf(var + BN_EPS);
    a[j] = s;
    c[j] = beta[j] - mean * s;
}

// ---------------- gather aggregation: one warp per destination node ---------
__global__ void k_gather(int N) {
    int w = (blockIdx.x * blockDim.x + threadIdx.x) >> 5;
    int lane = threadIdx.x & 31;
    if (w >= N) return;
    int d = w;
    int beg = g_coff[d], end = g_coff[d + 1];
    float wd = g_dinv[d];

    // self loop
    float4 v = ((const float4*)(g_hc + (size_t)d * D))[lane];
    float w0 = wd * wd;
    float4 acc = make_float4(w0 * v.x, w0 * v.y, w0 * v.z, w0 * v.w);

    for (int j = beg; j < end; j += 32) {
        int myidx = 0;
        float myw = 0.f;
        if (j + lane < end) {
            myidx = g_csr[j + lane];
            myw = g_dinv[myidx] * wd;
        }
        int cnt = min(32, end - j);
        for (int t = 0; t < cnt; t++) {
            int s    = __shfl_sync(0xffffffffu, myidx, t);
            float ww = __shfl_sync(0xffffffffu, myw, t);
            float4 u = ((const float4*)(g_hc + (size_t)s * D))[lane];
            acc.x = fmaf(ww, u.x, acc.x);
            acc.y = fmaf(ww, u.y, acc.y);
            acc.z = fmaf(ww, u.z, acc.z);
            acc.w = fmaf(ww, u.w, acc.w);
        }
    }
    ((float4*)(g_acc + (size_t)d * D))[lane] = acc;
}

// ---------------- finalize: BN2 affine + relu; reset degi for next replay ---
__global__ void k_final(float* __restrict__ out, int N) {
    int tt = blockIdx.x * blockDim.x + threadIdx.x;
    int r = tt >> 5, lane = tt & 31;
    if (r >= N) return;
    if (lane == 0) g_degi[r] = 0;   // next graph replay starts clean
    float4 v = ((const float4*)(g_acc + (size_t)r * D))[lane];
    int c = lane * 4;
    v.x = fmaxf(fmaf(v.x, g_a2[c + 0], g_c2[c + 0]), 0.f);
    v.y = fmaxf(fmaf(v.y, g_a2[c + 1], g_c2[c + 1]), 0.f);
    v.z = fmaxf(fmaf(v.z, g_a2[c + 2], g_c2[c + 2]), 0.f);
    v.w = fmaxf(fmaf(v.w, g_a2[c + 3], g_c2[c + 3]), 0.f);
    ((float4*)(out + (size_t)r * D))[lane] = v;
}

// ---------------- launch ----------------
extern "C" void kernel_launch(void* const* d_in, const int* in_sizes, int n_in,
                              void* d_out, int out_size) {
    const float* x    = (const float*)d_in[0];
    const int*   ei   = (const int*)d_in[1];   // int64 in reference -> delivered int32
    const float* Wm   = (const float*)d_in[2];
    // d_in[3] = b_mlp  : cancels inside training-mode BatchNorm
    const float* gam1 = (const float*)d_in[4];
    const float* bet1 = (const float*)d_in[5];
    const float* Wc   = (const float*)d_in[6];
    // d_in[7] = b_conv : cancels inside training-mode BatchNorm
    const float* gam2 = (const float*)d_in[8];
    const float* bet2 = (const float*)d_in[9];
    float* out = (float*)d_out;

    const int N = in_sizes[0] / D;
    const int E = in_sizes[1] / 2;
    const int* srcp = ei;
    const int* dstp = ei + E;
    const float invN = 1.0f / (float)N;
    const int nchunks = (N + CHUNK - 1) / CHUNK;

    k_deg<<<(E + 255) / 256, 256>>>(dstp, E, N);
    k_scan1<<<nchunks, CHUNK>>>(N);
    k_scan2<<<1, MAXCHUNKS>>>(nchunks);
    k_gemm<0><<<(N + 127) / 128, 256>>>(x, Wm, N);   // 4th: ncu sample slot
    k_scan3<<<nchunks, CHUNK>>>(N);
    k_fill<<<(E + 255) / 256, 256>>>(srcp, dstp, E, N);
    k_colstats<<<256, 256>>>(N, 0);
    k_affine<<<1, 128>>>(gam1, bet1, invN, 0);
    k_gemm<1><<<(N + 127) / 128, 256>>>(nullptr, Wc, N);
    k_gather<<<(N * 32 + 255) / 256, 256>>>(N);
    k_colstats<<<256, 256>>>(N, 1);
    k_affine<<<1, 128>>>(gam2, bet2, invN, 1);
    k_final<<<(N * 32 + 255) / 256, 256>>>(out, N);
}

// round 9
// speedup vs baseline: 1.6857x; 1.0637x over previous
#include <cuda_runtime.h>
#include <cuda_bf16.h>
#include <stdint.h>

#define D 128
#define MAXN 50048
#define MAXE 600064
#define BN_EPS 1e-5f
#define CHUNK 512
#define MAXCHUNKS 128

// ---------------- scratch (no allocation allowed) ----------------
__device__ float g_h  [(size_t)MAXN * D];   // x@W_mlp (raw, pre-BN)
__device__ float g_hc [(size_t)MAXN * D];   // relu(bn1(h)) @ W_conv
__device__ float g_acc[(size_t)MAXN * D];   // GCN aggregation result
__device__ int   g_degi[MAXN];
__device__ float g_dinv[MAXN];
__device__ int   g_coff[MAXN + 1];
__device__ int   g_cursor[MAXN];
__device__ int   g_csr[MAXE];
__device__ int   g_part[MAXCHUNKS];
__device__ int   g_pbase[MAXCHUNKS];
__device__ float g_sum1[D], g_sq1[D], g_sum2[D], g_sq2[D];
__device__ float g_a1[D], g_c1[D], g_a2[D], g_c2[D];
__device__ int   g_ctr[4];                  // last-block counters (reset in k_final)
__device__ uint32_t g_Bph[2][64 * D];       // packed bf16 hi planes: [mat][k2*128+col]
__device__ uint32_t g_Bpl[2][64 * D];       // packed bf16 lo planes

// ---------------- bf16 split helpers ----------------
__device__ __forceinline__ void split_bf16(float v, float& hi, float& lo) {
    __nv_bfloat16 h = __float2bfloat16_rn(v);
    hi = __bfloat162float(h);
    lo = v - hi;
}
__device__ __forceinline__ uint32_t pack_bf16x2(float a, float b) {
    __nv_bfloat162 p = __floats2bfloat162_rn(a, b);
    return *reinterpret_cast<uint32_t*>(&p);
}
__device__ __forceinline__ void mma_bf16(float* c, const uint32_t* a,
                                         uint32_t b0, uint32_t b1) {
    asm volatile(
        "mma.sync.aligned.m16n8k16.row.col.f32.bf16.bf16.f32 "
        "{%0,%1,%2,%3}, {%4,%5,%6,%7}, {%8,%9}, {%0,%1,%2,%3};"
        : "+f"(c[0]), "+f"(c[1]), "+f"(c[2]), "+f"(c[3])
        : "r"(a[0]), "r"(a[1]), "r"(a[2]), "r"(a[3]), "r"(b0), "r"(b1));
}

// ---------------- degree histogram + weight packing ----------------
__global__ void k_deg(const int* __restrict__ dst, int E, int N, int EB,
                      const float* __restrict__ Wm, const float* __restrict__ Wc) {
    if (blockIdx.x < (unsigned)EB) {
        int e = blockIdx.x * blockDim.x + threadIdx.x;
        if (e < E) {
            int d = dst[e];
            if ((unsigned)d < (unsigned)N) atomicAdd(&g_degi[d], 1);
        }
    } else {
        // pack Wm (m=0) and Wc (m=1) into bf16 hi/lo k-paired planes
        int idx = (blockIdx.x - EB) * blockDim.x + threadIdx.x;  // 0..16383
        if (idx < 2 * 64 * D) {
            int m = idx >> 13;
            int rest = idx & 8191;         // k2*128 + col
            int k2 = rest >> 7, col = rest & 127;
            const float* W = (m == 0) ? Wm : Wc;
            float v0 = W[(2 * k2) * D + col];
            float v1 = W[(2 * k2 + 1) * D + col];
            float h0, l0, h1, l1;
            split_bf16(v0, h0, l0);
            split_bf16(v1, h1, l1);
            g_Bph[m][rest] = pack_bf16x2(h0, h1);
            g_Bpl[m][rest] = pack_bf16x2(l0, l1);
        }
    }
}

// ---------------- scan phase 1 (+ phase 2 in last block) ----------------
__global__ void k_scan1(int N, int nchunks) {
    __shared__ int red[CHUNK];
    __shared__ int lastblk;
    int tid = threadIdx.x;
    int i = blockIdx.x * CHUNK + tid;
    red[tid] = (i < N) ? g_degi[i] : 0;
    __syncthreads();
    #pragma unroll
    for (int off = CHUNK / 2; off > 0; off >>= 1) {
        if (tid < off) red[tid] += red[tid + off];
        __syncthreads();
    }
    if (tid == 0) g_part[blockIdx.x] = red[0];
    __threadfence();
    __syncthreads();
    if (tid == 0) {
        int ret = atomicAdd(&g_ctr[2], 1);
        lastblk = (ret == gridDim.x - 1);
    }
    __syncthreads();
    if (!lastblk) return;

    // ---- phase 2 (last block only): scan chunk sums + zero BN stats ----
    __shared__ int s[MAXCHUNKS];
    if (tid < D) { g_sum1[tid] = 0.f; g_sq1[tid] = 0.f; g_sum2[tid] = 0.f; g_sq2[tid] = 0.f; }
    if (tid < MAXCHUNKS)
        s[tid] = (tid < nchunks) ? __ldcg(&g_part[tid]) : 0;
    __syncthreads();
    #pragma unroll
    for (int off = 1; off < MAXCHUNKS; off <<= 1) {
        int v = 0, u = 0;
        if (tid < MAXCHUNKS) { v = s[tid]; u = (tid >= off) ? s[tid - off] : 0; }
        __syncthreads();
        if (tid < MAXCHUNKS) s[tid] = v + u;
        __syncthreads();
    }
    if (tid < nchunks) g_pbase[tid] = (tid > 0) ? s[tid - 1] : 0;
}

__global__ void k_scan3(int N) {
    __shared__ int s[CHUNK];
    int tid = threadIdx.x;
    int i = blockIdx.x * CHUNK + tid;
    int deg = (i < N) ? g_degi[i] : 0;
    s[tid] = deg;
    __syncthreads();
    #pragma unroll
    for (int off = 1; off < CHUNK; off <<= 1) {
        int v = s[tid];
        int u = (tid >= off) ? s[tid - off] : 0;
        __syncthreads();
        s[tid] = v + u;
        __syncthreads();
    }
    if (i < N) {
        int base = g_pbase[blockIdx.x];
        int excl = base + s[tid] - deg;
        g_coff[i] = excl;
        g_cursor[i] = excl;
        g_dinv[i] = rsqrtf((float)deg + 1.0f);   // +1 self loop
        if (i == N - 1) g_coff[N] = excl + deg;
    }
}

// ---------------- CSR fill ----------------
__global__ void k_fill(const int* __restrict__ src,
                       const int* __restrict__ dst, int E, int N) {
    int e = blockIdx.x * blockDim.x + threadIdx.x;
    if (e < E) {
        int d = dst[e], s = src[e];
        if ((unsigned)d < (unsigned)N && (unsigned)s < (unsigned)N) {
            int pos = atomicAdd(&g_cursor[d], 1);
            g_csr[pos] = s;
        }
    }
}

// ---------------- bf16x3 MMA GEMM, fully pipelined -------------------------
// C[M,128] = act(A[M,128]) @ B[128,128]. 8 warps x 16 rows, k-chunk 16.
// B pre-packed in global planes; A register-prefetched + converted post-MMA.
// One __syncthreads per chunk. MODE 0: A=x -> g_h. MODE 1: A=g_h+BN1 -> g_hc.
#define APST 12
#define BPST 136
template <int MODE>
__global__ void __launch_bounds__(256, 2) k_gemm(const float* __restrict__ Ain, int M) {
    __shared__ uint32_t Ahp[2][128 * APST], Alp[2][128 * APST];
    __shared__ uint32_t Bhp[2][8 * BPST],   Blp[2][8 * BPST];
    const float* A = (MODE == 0) ? Ain : g_h;
    float*       C = (MODE == 0) ? g_h : g_hc;

    const int tid  = threadIdx.x;
    const int w    = tid >> 5;
    const int lane = tid & 31;
    const int g    = lane >> 2;
    const int t    = lane & 3;
    const int row0 = blockIdx.x * 128;

    // A staging coords (2 float4 per thread)
    const int r0_ = tid >> 2,        c40 = tid & 3;
    const int r1_ = (tid + 256) >> 2, c41 = (tid + 256) & 3;
    const int gr0 = row0 + r0_, gr1 = row0 + r1_;

    float acc[16][4];
    #pragma unroll
    for (int n = 0; n < 16; n++)
        #pragma unroll
        for (int i = 0; i < 4; i++) acc[n][i] = 0.f;

    auto loadA = [&](int kk, float4& v0, float4& v1) {
        v0 = make_float4(0.f, 0.f, 0.f, 0.f);
        v1 = make_float4(0.f, 0.f, 0.f, 0.f);
        if (gr0 < M) v0 = *(const float4*)(A + (size_t)gr0 * D + kk + c40 * 4);
        if (gr1 < M) v1 = *(const float4*)(A + (size_t)gr1 * D + kk + c41 * 4);
    };
    auto convertA = [&](int kk, int buf, float4 v0, float4 v1) {
        #pragma unroll
        for (int i = 0; i < 2; i++) {
            float4 v = i ? v1 : v0;
            int r = i ? r1_ : r0_;
            int c4 = i ? c41 : c40;
            if (MODE == 1) {
                int c = kk + c4 * 4;
                v.x = fmaxf(fmaf(v.x, g_a1[c + 0], g_c1[c + 0]), 0.f);
                v.y = fmaxf(fmaf(v.y, g_a1[c + 1], g_c1[c + 1]), 0.f);
                v.z = fmaxf(fmaf(v.z, g_a1[c + 2], g_c1[c + 2]), 0.f);
                v.w = fmaxf(fmaf(v.w, g_a1[c + 3], g_c1[c + 3]), 0.f);
            }
            float hx, lx, hy, ly, hz, lz, hw, lw;
            split_bf16(v.x, hx, lx); split_bf16(v.y, hy, ly);
            split_bf16(v.z, hz, lz); split_bf16(v.w, hw, lw);
            uint32_t* ph = &Ahp[buf][r * APST + c4 * 2];
            uint32_t* pl = &Alp[buf][r * APST + c4 * 2];
            ph[0] = pack_bf16x2(hx, hy); ph[1] = pack_bf16x2(hz, hw);
            pl[0] = pack_bf16x2(lx, ly); pl[1] = pack_bf16x2(lz, lw);
        }
    };
    auto issueB = [&](int c, int buf) {
        int k2l = tid >> 5, c4 = tid & 31;
        int srcw = (c * 8 + k2l) * D + c4 * 4;
        uint32_t dh = (uint32_t)__cvta_generic_to_shared(&Bhp[buf][k2l * BPST + c4 * 4]);
        uint32_t dl = (uint32_t)__cvta_generic_to_shared(&Blp[buf][k2l * BPST + c4 * 4]);
        asm volatile("cp.async.cg.shared.global [%0], [%1], 16;\n"
                     :: "r"(dh), "l"(&g_Bph[MODE][srcw]));
        asm volatile("cp.async.cg.shared.global [%0], [%1], 16;\n"
                     :: "r"(dl), "l"(&g_Bpl[MODE][srcw]));
        asm volatile("cp.async.commit_group;\n");
    };

    // ---- prolog ----
    {
        float4 v0, v1;
        loadA(0, v0, v1);
        issueB(0, 0);
        convertA(0, 0, v0, v1);
        asm volatile("cp.async.wait_group 0;\n");
    }
    __syncthreads();

    for (int c = 0; c < 8; c++) {
        const int buf = c & 1, nb = buf ^ 1;
        const int kk = c * 16;
        float4 v0, v1;
        if (c < 7) {
            loadA(kk + 16, v0, v1);     // LDGs in flight across the MMA section
            issueB(c + 1, nb);
        }

        uint32_t ah[4], al[4];
        {
            int ra = (w * 16 + g) * APST + t;
            int rb = (w * 16 + g + 8) * APST + t;
            ah[0] = Ahp[buf][ra];     ah[1] = Ahp[buf][rb];
            ah[2] = Ahp[buf][ra + 4]; ah[3] = Ahp[buf][rb + 4];
            al[0] = Alp[buf][ra];     al[1] = Alp[buf][rb];
            al[2] = Alp[buf][ra + 4]; al[3] = Alp[buf][rb + 4];
        }
        #pragma unroll
        for (int nt = 0; nt < 16; nt++) {
            int bi = t * BPST + nt * 8 + g;
            uint32_t bh0 = Bhp[buf][bi], bh1 = Bhp[buf][bi + 4 * BPST];
            uint32_t bl0 = Blp[buf][bi], bl1 = Blp[buf][bi + 4 * BPST];
            mma_bf16(acc[nt], ah, bh0, bh1);   // hi*hi
            mma_bf16(acc[nt], ah, bl0, bl1);   // hi*lo
            mma_bf16(acc[nt], al, bh0, bh1);   // lo*hi
        }

        if (c < 7) {
            convertA(kk + 16, nb, v0, v1);      // LDG latency already covered
            asm volatile("cp.async.wait_group 0;\n");
            __syncthreads();
        }
    }

    // ---- store ----
    int rA = row0 + w * 16 + g;
    int rB = rA + 8;
    #pragma unroll
    for (int nt = 0; nt < 16; nt++) {
        int col = nt * 8 + 2 * t;
        if (rA < M)
            *(float2*)(C + (size_t)rA * D + col) = make_float2(acc[nt][0], acc[nt][1]);
        if (rB < M)
            *(float2*)(C + (size_t)rB * D + col) = make_float2(acc[nt][2], acc[nt][3]);
    }
}

// ---------------- colstats (+ fused BN affine in last block) ----------------
__global__ void k_colstats(int M, int which,
                           const float* __restrict__ gamma,
                           const float* __restrict__ beta, float invN) {
    const float* X = (which == 0) ? g_h : g_acc;
    float* sum = (which == 0) ? g_sum1 : g_sum2;
    float* sq  = (which == 0) ? g_sq1  : g_sq2;
    __shared__ float ss[8][D], sr[8][D];
    __shared__ int lastblk;
    int tid = threadIdx.x;
    int wid = tid >> 5, lane = tid & 31;
    float4 s = make_float4(0.f, 0.f, 0.f, 0.f);
    float4 q = make_float4(0.f, 0.f, 0.f, 0.f);
    for (int r = blockIdx.x * 8 + wid; r < M; r += gridDim.x * 8) {
        float4 v = ((const float4*)(X + (size_t)r * D))[lane];
        s.x += v.x; s.y += v.y; s.z += v.z; s.w += v.w;
        q.x += v.x * v.x; q.y += v.y * v.y; q.z += v.z * v.z; q.w += v.w * v.w;
    }
    ((float4*)ss[wid])[lane] = s;
    ((float4*)sr[wid])[lane] = q;
    __syncthreads();
    if (tid < D) {
        float a = 0.f, b = 0.f;
        #pragma unroll
        for (int wv = 0; wv < 8; wv++) { a += ss[wv][tid]; b += sr[wv][tid]; }
        atomicAdd(&sum[tid], a);
        atomicAdd(&sq[tid], b);
    }
    __threadfence();
    __syncthreads();
    if (tid == 0) {
        int ret = atomicAdd(&g_ctr[which], 1);
        lastblk = (ret == gridDim.x - 1);
    }
    __syncthreads();
    if (lastblk && tid < D) {
        float* a = (which == 0) ? g_a1 : g_a2;
        float* c = (which == 0) ? g_c1 : g_c2;
        float mean = __ldcg(&sum[tid]) * invN;
        float var  = __ldcg(&sq[tid]) * invN - mean * mean;
        float sc = gamma[tid] * rsqrtf(var + BN_EPS);
        a[tid] = sc;
        c[tid] = beta[tid] - mean * sc;
    }
}

// ---------------- gather aggregation: one warp per destination node ---------
__global__ void k_gather(int N) {
    int w = (blockIdx.x * blockDim.x + threadIdx.x) >> 5;
    int lane = threadIdx.x & 31;
    if (w >= N) return;
    int d = w;
    int beg = g_coff[d], end = g_coff[d + 1];
    float wd = g_dinv[d];

    float4 v = ((const float4*)(g_hc + (size_t)d * D))[lane];
    float w0 = wd * wd;
    float4 acc = make_float4(w0 * v.x, w0 * v.y, w0 * v.z, w0 * v.w);

    for (int j = beg; j < end; j += 32) {
        int myidx = 0;
        float myw = 0.f;
        if (j + lane < end) {
            myidx = g_csr[j + lane];
            myw = g_dinv[myidx] * wd;
        }
        int cnt = min(32, end - j);
        int t = 0;
        for (; t + 1 < cnt; t += 2) {   // 2-way MLP on neighbor rows
            int s0    = __shfl_sync(0xffffffffu, myidx, t);
            float ww0 = __shfl_sync(0xffffffffu, myw, t);
            int s1    = __shfl_sync(0xffffffffu, myidx, t + 1);
            float ww1 = __shfl_sync(0xffffffffu, myw, t + 1);
            float4 u0 = ((const float4*)(g_hc + (size_t)s0 * D))[lane];
            float4 u1 = ((const float4*)(g_hc + (size_t)s1 * D))[lane];
            acc.x = fmaf(ww0, u0.x, acc.x); acc.y = fmaf(ww0, u0.y, acc.y);
            acc.z = fmaf(ww0, u0.z, acc.z); acc.w = fmaf(ww0, u0.w, acc.w);
            acc.x = fmaf(ww1, u1.x, acc.x); acc.y = fmaf(ww1, u1.y, acc.y);
            acc.z = fmaf(ww1, u1.z, acc.z); acc.w = fmaf(ww1, u1.w, acc.w);
        }
        if (t < cnt) {
            int s0    = __shfl_sync(0xffffffffu, myidx, t);
            float ww0 = __shfl_sync(0xffffffffu, myw, t);
            float4 u0 = ((const float4*)(g_hc + (size_t)s0 * D))[lane];
            acc.x = fmaf(ww0, u0.x, acc.x); acc.y = fmaf(ww0, u0.y, acc.y);
            acc.z = fmaf(ww0, u0.z, acc.z); acc.w = fmaf(ww0, u0.w, acc.w);
        }
    }
    ((float4*)(g_acc + (size_t)d * D))[lane] = acc;
}

// ---------------- finalize: BN2 affine + relu; reset state for next replay --
__global__ void k_final(float* __restrict__ out, int N) {
    int tt = blockIdx.x * blockDim.x + threadIdx.x;
    int r = tt >> 5, lane = tt & 31;
    if (blockIdx.x == 0 && threadIdx.x < 4) g_ctr[threadIdx.x] = 0;
    if (r >= N) return;
    if (lane == 0) g_degi[r] = 0;
    float4 v = ((const float4*)(g_acc + (size_t)r * D))[lane];
    int c = lane * 4;
    v.x = fmaxf(fmaf(v.x, g_a2[c + 0], g_c2[c + 0]), 0.f);
    v.y = fmaxf(fmaf(v.y, g_a2[c + 1], g_c2[c + 1]), 0.f);
    v.z = fmaxf(fmaf(v.z, g_a2[c + 2], g_c2[c + 2]), 0.f);
    v.w = fmaxf(fmaf(v.w, g_a2[c + 3], g_c2[c + 3]), 0.f);
    ((float4*)(out + (size_t)r * D))[lane] = v;
}

// ---------------- launch ----------------
extern "C" void kernel_launch(void* const* d_in, const int* in_sizes, int n_in,
                              void* d_out, int out_size) {
    const float* x    = (const float*)d_in[0];
    const int*   ei   = (const int*)d_in[1];   // int64 in reference -> delivered int32
    const float* Wm   = (const float*)d_in[2];
    // d_in[3] = b_mlp  : cancels inside training-mode BatchNorm
    const float* gam1 = (const float*)d_in[4];
    const float* bet1 = (const float*)d_in[5];
    const float* Wc   = (const float*)d_in[6];
    // d_in[7] = b_conv : cancels inside training-mode BatchNorm
    const float* gam2 = (const float*)d_in[8];
    const float* bet2 = (const float*)d_in[9];
    float* out = (float*)d_out;

    const int N = in_sizes[0] / D;
    const int E = in_sizes[1] / 2;
    const int* srcp = ei;
    const int* dstp = ei + E;
    const float invN = 1.0f / (float)N;
    const int nchunks = (N + CHUNK - 1) / CHUNK;
    const int EB = (E + 255) / 256;

    k_deg<<<EB + 64, 256>>>(dstp, E, N, EB, Wm, Wc);     // + weight packing
    k_scan1<<<nchunks, CHUNK>>>(N, nchunks);              // + scan2 in last block
    k_scan3<<<nchunks, CHUNK>>>(N);
    k_gemm<0><<<(N + 127) / 128, 256>>>(x, N);            // 4th: ncu sample slot
    k_fill<<<(E + 255) / 256, 256>>>(srcp, dstp, E, N);
    k_colstats<<<256, 256>>>(N, 0, gam1, bet1, invN);     // + affine in last block
    k_gemm<1><<<(N + 127) / 128, 256>>>(nullptr, N);
    k_gather<<<(N * 32 + 255) / 256, 256>>>(N);
    k_colstats<<<256, 256>>>(N, 1, gam2, bet2, invN);     // + affine in last block
    k_final<<<(N * 32 + 255) / 256, 256>>>(out, N);
}

// round 13
// speedup vs baseline: 1.8640x; 1.1058x over previous
#include <cuda_runtime.h>
#include <cuda_bf16.h>
#include <stdint.h>

#define D 128
#define MAXN 50048
#define MAXE 600064
#define BN_EPS 1e-5f
#define MAXCHUNKS 128

// ---------------- scratch (no allocation allowed) ----------------
__device__ float g_h  [(size_t)MAXN * D];   // x@W_mlp (raw, pre-BN)
__device__ float g_hc [(size_t)MAXN * D];   // relu(bn1(h)) @ W_conv
__device__ float g_acc[(size_t)MAXN * D];   // GCN aggregation result
__device__ int   g_degi[MAXN];
__device__ float g_dinv[MAXN];
__device__ int   g_coff[MAXN + 1];
__device__ int   g_cursor[MAXN];
__device__ int   g_csr[MAXE];
__device__ int   g_part[MAXCHUNKS];
__device__ int   g_pbase[MAXCHUNKS];
__device__ float g_sum1[D], g_sq1[D], g_sum2[D], g_sq2[D];
__device__ float g_a1[D], g_c1[D], g_a2[D], g_c2[D];
__device__ int   g_ctr[4];                  // last-block counters (reset in k_final)
__device__ uint32_t g_Bph[2][64 * D];       // packed bf16 hi planes: [mat][k2*128+col]
__device__ uint32_t g_Bpl[2][64 * D];       // packed bf16 lo planes

// ---------------- bf16 split helpers ----------------
__device__ __forceinline__ void split_bf16(float v, float& hi, float& lo) {
    __nv_bfloat16 h = __float2bfloat16_rn(v);
    hi = __bfloat162float(h);
    lo = v - hi;
}
__device__ __forceinline__ uint32_t pack_bf16x2(float a, float b) {
    __nv_bfloat162 p = __floats2bfloat162_rn(a, b);
    return *reinterpret_cast<uint32_t*>(&p);
}
__device__ __forceinline__ void mma_bf16(float* c, const uint32_t* a,
                                         uint32_t b0, uint32_t b1) {
    asm volatile(
        "mma.sync.aligned.m16n8k16.row.col.f32.bf16.bf16.f32 "
        "{%0,%1,%2,%3}, {%4,%5,%6,%7}, {%8,%9}, {%0,%1,%2,%3};"
        : "+f"(c[0]), "+f"(c[1]), "+f"(c[2]), "+f"(c[3])
        : "r"(a[0]), "r"(a[1]), "r"(a[2]), "r"(a[3]), "r"(b0), "r"(b1));
}

// ---------------- weight packing (both mats) ----------------
__global__ void k_pack(const float* __restrict__ Wm, const float* __restrict__ Wc) {
    int idx = blockIdx.x * blockDim.x + threadIdx.x;   // 0..16383
    if (idx < 2 * 64 * D) {
        int m = idx >> 13;
        int rest = idx & 8191;         // k2*128 + col
        int k2 = rest >> 7, col = rest & 127;
        const float* W = (m == 0) ? Wm : Wc;
        float v0 = W[(2 * k2) * D + col];
        float v1 = W[(2 * k2 + 1) * D + col];
        float h0, l0, h1, l1;
        split_bf16(v0, h0, l0);
        split_bf16(v1, h1, l1);
        g_Bph[m][rest] = pack_bf16x2(h0, h1);
        g_Bpl[m][rest] = pack_bf16x2(l0, l1);
    }
}

// ---------------- bf16x3 MMA GEMM body (R9-proven pipeline) -----------------
// C[M,128] = act(A[M,128]) @ B[128,128]. 8 warps x 16 rows, k-chunk 16.
// One __syncthreads per chunk; B pre-packed; A register-prefetched.
// All 16-byte-accessed shared arrays are explicitly 16B-aligned (R11 lesson).
#define APST 12
#define BPST 136
template <int MODE>
__device__ __forceinline__ void gemm_body(const float* __restrict__ Ain, int M, int blk) {
    __shared__ __align__(16) uint32_t Ahp[2][128 * APST], Alp[2][128 * APST];
    __shared__ __align__(16) uint32_t Bhp[2][8 * BPST],   Blp[2][8 * BPST];
    const float* A = (MODE == 0) ? Ain : g_h;
    float*       C = (MODE == 0) ? g_h : g_hc;

    const int tid  = threadIdx.x;
    const int w    = tid >> 5;
    const int lane = tid & 31;
    const int g    = lane >> 2;
    const int t    = lane & 3;
    const int row0 = blk * 128;

    const int r0_ = tid >> 2,         c40 = tid & 3;
    const int r1_ = (tid + 256) >> 2, c41 = (tid + 256) & 3;
    const int gr0 = row0 + r0_, gr1 = row0 + r1_;

    float acc[16][4];
    #pragma unroll
    for (int n = 0; n < 16; n++)
        #pragma unroll
        for (int i = 0; i < 4; i++) acc[n][i] = 0.f;

    auto loadA = [&](int kk, float4& v0, float4& v1) {
        v0 = make_float4(0.f, 0.f, 0.f, 0.f);
        v1 = make_float4(0.f, 0.f, 0.f, 0.f);
        if (gr0 < M) v0 = *(const float4*)(A + (size_t)gr0 * D + kk + c40 * 4);
        if (gr1 < M) v1 = *(const float4*)(A + (size_t)gr1 * D + kk + c41 * 4);
    };
    auto convertA = [&](int kk, int buf, float4 v0, float4 v1) {
        #pragma unroll
        for (int i = 0; i < 2; i++) {
            float4 v = i ? v1 : v0;
            int r = i ? r1_ : r0_;
            int c4 = i ? c41 : c40;
            if (MODE == 1) {
                int c = kk + c4 * 4;
                v.x = fmaxf(fmaf(v.x, g_a1[c + 0], g_c1[c + 0]), 0.f);
                v.y = fmaxf(fmaf(v.y, g_a1[c + 1], g_c1[c + 1]), 0.f);
                v.z = fmaxf(fmaf(v.z, g_a1[c + 2], g_c1[c + 2]), 0.f);
                v.w = fmaxf(fmaf(v.w, g_a1[c + 3], g_c1[c + 3]), 0.f);
            }
            float hx, lx, hy, ly, hz, lz, hw, lw;
            split_bf16(v.x, hx, lx); split_bf16(v.y, hy, ly);
            split_bf16(v.z, hz, lz); split_bf16(v.w, hw, lw);
            uint32_t* ph = &Ahp[buf][r * APST + c4 * 2];
            uint32_t* pl = &Alp[buf][r * APST + c4 * 2];
            ph[0] = pack_bf16x2(hx, hy); ph[1] = pack_bf16x2(hz, hw);
            pl[0] = pack_bf16x2(lx, ly); pl[1] = pack_bf16x2(lz, lw);
        }
    };
    auto issueB = [&](int c, int buf) {
        int k2l = tid >> 5, c4 = tid & 31;
        int srcw = (c * 8 + k2l) * D + c4 * 4;
        uint32_t dh = (uint32_t)__cvta_generic_to_shared(&Bhp[buf][k2l * BPST + c4 * 4]);
        uint32_t dl = (uint32_t)__cvta_generic_to_shared(&Blp[buf][k2l * BPST + c4 * 4]);
        asm volatile("cp.async.cg.shared.global [%0], [%1], 16;\n"
                     :: "r"(dh), "l"(&g_Bph[MODE][srcw]));
        asm volatile("cp.async.cg.shared.global [%0], [%1], 16;\n"
                     :: "r"(dl), "l"(&g_Bpl[MODE][srcw]));
        asm volatile("cp.async.commit_group;\n");
    };

    {
        float4 v0, v1;
        loadA(0, v0, v1);
        issueB(0, 0);
        convertA(0, 0, v0, v1);
        asm volatile("cp.async.wait_group 0;\n");
    }
    __syncthreads();

    for (int c = 0; c < 8; c++) {
        const int buf = c & 1, nb = buf ^ 1;
        const int kk = c * 16;
        float4 v0, v1;
        if (c < 7) {
            loadA(kk + 16, v0, v1);
            issueB(c + 1, nb);
        }

        uint32_t ah[4], al[4];
        {
            int ra = (w * 16 + g) * APST + t;
            int rb = (w * 16 + g + 8) * APST + t;
            ah[0] = Ahp[buf][ra];     ah[1] = Ahp[buf][rb];
            ah[2] = Ahp[buf][ra + 4]; ah[3] = Ahp[buf][rb + 4];
            al[0] = Alp[buf][ra];     al[1] = Alp[buf][rb];
            al[2] = Alp[buf][ra + 4]; al[3] = Alp[buf][rb + 4];
        }
        #pragma unroll
        for (int nt = 0; nt < 16; nt++) {
            int bi = t * BPST + nt * 8 + g;
            uint32_t bh0 = Bhp[buf][bi], bh1 = Bhp[buf][bi + 4 * BPST];
            uint32_t bl0 = Blp[buf][bi], bl1 = Blp[buf][bi + 4 * BPST];
            mma_bf16(acc[nt], ah, bh0, bh1);
            mma_bf16(acc[nt], ah, bl0, bl1);
            mma_bf16(acc[nt], al, bh0, bh1);
        }

        if (c < 7) {
            convertA(kk + 16, nb, v0, v1);
            asm volatile("cp.async.wait_group 0;\n");
            __syncthreads();
        }
    }

    int rA = row0 + w * 16 + g;
    int rB = rA + 8;
    #pragma unroll
    for (int nt = 0; nt < 16; nt++) {
        int col = nt * 8 + 2 * t;
        if (rA < M)
            *(float2*)(C + (size_t)rA * D + col) = make_float2(acc[nt][0], acc[nt][1]);
        if (rB < M)
            *(float2*)(C + (size_t)rB * D + col) = make_float2(acc[nt][2], acc[nt][3]);
    }
}

// ---------------- colstats body (which=0/1, + fused affine in last block) ---
__device__ __forceinline__ void colstats_body(int M, int which, int blk, int nblk,
                                              const float* __restrict__ gamma,
                                              const float* __restrict__ beta, float invN) {
    const float* X = (which == 0) ? g_h : g_acc;
    float* sum = (which == 0) ? g_sum1 : g_sum2;
    float* sq  = (which == 0) ? g_sq1  : g_sq2;
    __shared__ __align__(16) float ss[8][D], sr[8][D];
    __shared__ int lastblk;
    int tid = threadIdx.x;
    int wid = tid >> 5, lane = tid & 31;
    float4 s = make_float4(0.f, 0.f, 0.f, 0.f);
    float4 q = make_float4(0.f, 0.f, 0.f, 0.f);
    for (int r = blk * 8 + wid; r < M; r += nblk * 8) {
        float4 v = ((const float4*)(X + (size_t)r * D))[lane];
        s.x += v.x; s.y += v.y; s.z += v.z; s.w += v.w;
        q.x += v.x * v.x; q.y += v.y * v.y; q.z += v.z * v.z; q.w += v.w * v.w;
    }
    ((float4*)ss[wid])[lane] = s;
    ((float4*)sr[wid])[lane] = q;
    __syncthreads();
    if (tid < D) {
        float a = 0.f, b = 0.f;
        #pragma unroll
        for (int wv = 0; wv < 8; wv++) { a += ss[wv][tid]; b += sr[wv][tid]; }
        atomicAdd(&sum[tid], a);
        atomicAdd(&sq[tid], b);
    }
    __threadfence();
    __syncthreads();
    if (tid == 0) {
        int ret = atomicAdd(&g_ctr[which], 1);
        lastblk = (ret == nblk - 1);
    }
    __syncthreads();
    if (lastblk && tid < D) {
        float* a = (which == 0) ? g_a1 : g_a2;
        float* c = (which == 0) ? g_c1 : g_c2;
        float mean = __ldcg(&sum[tid]) * invN;
        float var  = __ldcg(&sq[tid]) * invN - mean * mean;
        float sc = gamma[tid] * rsqrtf(var + BN_EPS);
        a[tid] = sc;
        c[tid] = beta[tid] - mean * sc;
    }
}

// ---------------- merged kernel 2: gemm0 + degree histogram -----------------
__global__ void __launch_bounds__(256, 2) k_g0(const float* __restrict__ x,
                                               const int* __restrict__ dst,
                                               int E, int N, int GB) {
    if ((int)blockIdx.x < GB) {
        gemm_body<0>(x, N, blockIdx.x);
    } else {
        int e = (blockIdx.x - GB) * 256 + threadIdx.x;
        if (e < E) {
            int d = dst[e];
            if ((unsigned)d < (unsigned)N) atomicAdd(&g_degi[d], 1);
        }
    }
}

// ---------------- merged kernel 3: colstats0 + scan1 (phase2 in last block) -
__global__ void k_cs0s1(int N, const float* __restrict__ gam1,
                        const float* __restrict__ bet1, float invN, int nchunks) {
    if (blockIdx.x < 256) {
        colstats_body(N, 0, blockIdx.x, 256, gam1, bet1, invN);
        return;
    }
    // ---- scan1: per-chunk degree sums (256 thr, 2 elems each) ----
    __shared__ int red[256];
    __shared__ int lastblk1;
    int chunk = blockIdx.x - 256;
    int tid = threadIdx.x;
    int i0 = chunk * 512 + 2 * tid;
    int d0 = (i0 < N) ? g_degi[i0] : 0;
    int d1 = (i0 + 1 < N) ? g_degi[i0 + 1] : 0;
    red[tid] = d0 + d1;
    __syncthreads();
    #pragma unroll
    for (int off = 128; off > 0; off >>= 1) {
        if (tid < off) red[tid] += red[tid + off];
        __syncthreads();
    }
    if (tid == 0) g_part[chunk] = red[0];
    __threadfence();
    __syncthreads();
    if (tid == 0) {
        int ret = atomicAdd(&g_ctr[2], 1);
        lastblk1 = (ret == nchunks - 1);
    }
    __syncthreads();
    if (!lastblk1) return;

    __shared__ int s[MAXCHUNKS];
    if (tid < MAXCHUNKS)
        s[tid] = (tid < nchunks) ? __ldcg(&g_part[tid]) : 0;
    __syncthreads();
    #pragma unroll
    for (int off = 1; off < MAXCHUNKS; off <<= 1) {
        int v = 0, u = 0;
        if (tid < MAXCHUNKS) { v = s[tid]; u = (tid >= off) ? s[tid - off] : 0; }
        __syncthreads();
        if (tid < MAXCHUNKS) s[tid] = v + u;
        __syncthreads();
    }
    if (tid < nchunks) g_pbase[tid] = (tid > 0) ? s[tid - 1] : 0;
}

// ---------------- merged kernel 4: gemm1 + scan3 ----------------------------
__global__ void __launch_bounds__(256, 2) k_g1s3(int N, int GB) {
    if ((int)blockIdx.x < GB) {
        gemm_body<1>(nullptr, N, blockIdx.x);
        return;
    }
    // ---- scan3: intra-chunk exclusive scan + dinv (256 thr, pair scan) ----
    __shared__ int sp[256];
    int chunk = blockIdx.x - GB;
    int tid = threadIdx.x;
    int i0 = chunk * 512 + 2 * tid;
    int d0 = (i0 < N) ? g_degi[i0] : 0;
    int d1 = (i0 + 1 < N) ? g_degi[i0 + 1] : 0;
    int ps = d0 + d1;
    sp[tid] = ps;
    __syncthreads();
    #pragma unroll
    for (int off = 1; off < 256; off <<= 1) {
        int v = sp[tid];
        int u = (tid >= off) ? sp[tid - off] : 0;
        __syncthreads();
        sp[tid] = v + u;
        __syncthreads();
    }
    int base = g_pbase[chunk];
    int excl = base + sp[tid] - ps;
    if (i0 < N) {
        g_coff[i0] = excl;
        g_cursor[i0] = excl;
        g_dinv[i0] = rsqrtf((float)d0 + 1.0f);
        if (i0 == N - 1) g_coff[N] = excl + d0;
    }
    if (i0 + 1 < N) {
        g_coff[i0 + 1] = excl + d0;
        g_cursor[i0 + 1] = excl + d0;
        g_dinv[i0 + 1] = rsqrtf((float)d1 + 1.0f);
        if (i0 + 1 == N - 1) g_coff[N] = excl + d0 + d1;
    }
}

// ---------------- CSR fill ----------------
__global__ void k_fill(const int* __restrict__ src,
                       const int* __restrict__ dst, int E, int N) {
    int e = blockIdx.x * blockDim.x + threadIdx.x;
    if (e < E) {
        int d = dst[e], s = src[e];
        if ((unsigned)d < (unsigned)N && (unsigned)s < (unsigned)N) {
            int pos = atomicAdd(&g_cursor[d], 1);
            g_csr[pos] = s;
        }
    }
}

// ---------------- standalone colstats (which=1) ----------------
__global__ void k_colstats(int M, int which,
                           const float* __restrict__ gamma,
                           const float* __restrict__ beta, float invN) {
    colstats_body(M, which, blockIdx.x, gridDim.x, gamma, beta, invN);
}

// ---------------- gather aggregation: one warp per destination node ---------
__global__ void k_gather(int N) {
    int w = (blockIdx.x * blockDim.x + threadIdx.x) >> 5;
    int lane = threadIdx.x & 31;
    if (w >= N) return;
    int d = w;
    int beg = g_coff[d], end = g_coff[d + 1];
    float wd = g_dinv[d];

    float4 v = ((const float4*)(g_hc + (size_t)d * D))[lane];
    float w0 = wd * wd;
    float4 acc = make_float4(w0 * v.x, w0 * v.y, w0 * v.z, w0 * v.w);

    for (int j = beg; j < end; j += 32) {
        int myidx = 0;
        float myw = 0.f;
        if (j + lane < end) {
            myidx = g_csr[j + lane];
            myw = g_dinv[myidx] * wd;
        }
        int cnt = min(32, end - j);
        int t = 0;
        for (; t + 1 < cnt; t += 2) {
            int s0    = __shfl_sync(0xffffffffu, myidx, t);
            float ww0 = __shfl_sync(0xffffffffu, myw, t);
            int s1    = __shfl_sync(0xffffffffu, myidx, t + 1);
            float ww1 = __shfl_sync(0xffffffffu, myw, t + 1);
            float4 u0 = ((const float4*)(g_hc + (size_t)s0 * D))[lane];
            float4 u1 = ((const float4*)(g_hc + (size_t)s1 * D))[lane];
            acc.x = fmaf(ww0, u0.x, acc.x); acc.y = fmaf(ww0, u0.y, acc.y);
            acc.z = fmaf(ww0, u0.z, acc.z); acc.w = fmaf(ww0, u0.w, acc.w);
            acc.x = fmaf(ww1, u1.x, acc.x); acc.y = fmaf(ww1, u1.y, acc.y);
            acc.z = fmaf(ww1, u1.z, acc.z); acc.w = fmaf(ww1, u1.w, acc.w);
        }
        if (t < cnt) {
            int s0    = __shfl_sync(0xffffffffu, myidx, t);
            float ww0 = __shfl_sync(0xffffffffu, myw, t);
            float4 u0 = ((const float4*)(g_hc + (size_t)s0 * D))[lane];
            acc.x = fmaf(ww0, u0.x, acc.x); acc.y = fmaf(ww0, u0.y, acc.y);
            acc.z = fmaf(ww0, u0.z, acc.z); acc.w = fmaf(ww0, u0.w, acc.w);
        }
    }
    ((float4*)(g_acc + (size_t)d * D))[lane] = acc;
}

// ---------------- finalize: BN2 affine + relu; reset ALL cross-call state ---
__global__ void k_final(float* __restrict__ out, int N) {
    int tt = blockIdx.x * blockDim.x + threadIdx.x;
    int r = tt >> 5, lane = tt & 31;
    if (blockIdx.x == 0) {
        if (threadIdx.x < 4) g_ctr[threadIdx.x] = 0;
        if (threadIdx.x < D) {      // reset BN stat accumulators for next replay
            g_sum1[threadIdx.x] = 0.f; g_sq1[threadIdx.x] = 0.f;
            g_sum2[threadIdx.x] = 0.f; g_sq2[threadIdx.x] = 0.f;
        }
    }
    if (r >= N) return;
    if (lane == 0) g_degi[r] = 0;
    float4 v = ((const float4*)(g_acc + (size_t)r * D))[lane];
    int c = lane * 4;
    v.x = fmaxf(fmaf(v.x, g_a2[c + 0], g_c2[c + 0]), 0.f);
    v.y = fmaxf(fmaf(v.y, g_a2[c + 1], g_c2[c + 1]), 0.f);
    v.z = fmaxf(fmaf(v.z, g_a2[c + 2], g_c2[c + 2]), 0.f);
    v.w = fmaxf(fmaf(v.w, g_a2[c + 3], g_c2[c + 3]), 0.f);
    ((float4*)(out + (size_t)r * D))[lane] = v;
}

// ---------------- launch ----------------
extern "C" void kernel_launch(void* const* d_in, const int* in_sizes, int n_in,
                              void* d_out, int out_size) {
    const float* x    = (const float*)d_in[0];
    const int*   ei   = (const int*)d_in[1];   // int64 in reference -> delivered int32
    const float* Wm   = (const float*)d_in[2];
    // d_in[3] = b_mlp  : cancels inside training-mode BatchNorm
    const float* gam1 = (const float*)d_in[4];
    const float* bet1 = (const float*)d_in[5];
    const float* Wc   = (const float*)d_in[6];
    // d_in[7] = b_conv : cancels inside training-mode BatchNorm
    const float* gam2 = (const float*)d_in[8];
    const float* bet2 = (const float*)d_in[9];
    float* out = (float*)d_out;

    const int N = in_sizes[0] / D;
    const int E = in_sizes[1] / 2;
    const int* srcp = ei;
    const int* dstp = ei + E;
    const float invN = 1.0f / (float)N;
    const int nchunks = (N + 511) / 512;
    const int EB = (E + 255) / 256;
    const int GB = (N + 127) / 128;

    k_pack<<<64, 256>>>(Wm, Wc);
    k_g0<<<GB + EB, 256>>>(x, dstp, E, N, GB);            // gemm0 + deg
    k_cs0s1<<<256 + nchunks, 256>>>(N, gam1, bet1, invN, nchunks);  // colstats0 + scan1/2
    k_g1s3<<<GB + nchunks, 256>>>(N, GB);                 // gemm1 + scan3 (ncu slot)
    k_fill<<<(E + 255) / 256, 256>>>(srcp, dstp, E, N);
    k_gather<<<(N * 32 + 255) / 256, 256>>>(N);
    k_colstats<<<256, 256>>>(N, 1, gam2, bet2, invN);
    k_final<<<(N * 32 + 255) / 256, 256>>>(out, N);
}

// round 14
// speedup vs baseline: 1.9351x; 1.0381x over previous
#include <cuda_runtime.h>
#include <cuda_bf16.h>
#include <cuda_fp16.h>
#include <stdint.h>

#define D 128
#define MAXN 50048
#define MAXE 600064
#define BN_EPS 1e-5f
#define MAXCHUNKS 128

// ---------------- scratch (no allocation allowed) ----------------
__device__ float  g_h  [(size_t)MAXN * D];  // x@W_mlp (raw, pre-BN)
__device__ __half g_hch[(size_t)MAXN * D];  // relu(bn1(h)) @ W_conv, fp16 (gather-only)
__device__ float  g_acc[(size_t)MAXN * D];  // GCN aggregation result
__device__ int    g_degi[MAXN];
__device__ float  g_dinv[MAXN];
__device__ int    g_coff[MAXN + 1];
__device__ int    g_cursor[MAXN];
__device__ int    g_csr[MAXE];
__device__ int    g_part[MAXCHUNKS];
__device__ int    g_pbase[MAXCHUNKS];
__device__ float  g_sum1[D], g_sq1[D], g_sum2[D], g_sq2[D];
__device__ float  g_a1[D], g_c1[D], g_a2[D], g_c2[D];
__device__ int    g_ctr[4];                 // last-block counters (reset in k_final)
__device__ uint32_t g_Bph[2][64 * D];       // packed bf16 hi planes: [mat][k2*128+col]
__device__ uint32_t g_Bpl[2][64 * D];       // packed bf16 lo planes

// ---------------- bf16 split helpers ----------------
__device__ __forceinline__ void split_bf16(float v, float& hi, float& lo) {
    __nv_bfloat16 h = __float2bfloat16_rn(v);
    hi = __bfloat162float(h);
    lo = v - hi;
}
__device__ __forceinline__ uint32_t pack_bf16x2(float a, float b) {
    __nv_bfloat162 p = __floats2bfloat162_rn(a, b);
    return *reinterpret_cast<uint32_t*>(&p);
}
__device__ __forceinline__ void mma_bf16(float* c, const uint32_t* a,
                                         uint32_t b0, uint32_t b1) {
    asm volatile(
        "mma.sync.aligned.m16n8k16.row.col.f32.bf16.bf16.f32 "
        "{%0,%1,%2,%3}, {%4,%5,%6,%7}, {%8,%9}, {%0,%1,%2,%3};"
        : "+f"(c[0]), "+f"(c[1]), "+f"(c[2]), "+f"(c[3])
        : "r"(a[0]), "r"(a[1]), "r"(a[2]), "r"(a[3]), "r"(b0), "r"(b1));
}

// ---------------- weight packing (both mats) ----------------
__global__ void k_pack(const float* __restrict__ Wm, const float* __restrict__ Wc) {
    int idx = blockIdx.x * blockDim.x + threadIdx.x;   // 0..16383
    if (idx < 2 * 64 * D) {
        int m = idx >> 13;
        int rest = idx & 8191;         // k2*128 + col
        int k2 = rest >> 7, col = rest & 127;
        const float* W = (m == 0) ? Wm : Wc;
        float v0 = W[(2 * k2) * D + col];
        float v1 = W[(2 * k2 + 1) * D + col];
        float h0, l0, h1, l1;
        split_bf16(v0, h0, l0);
        split_bf16(v1, h1, l1);
        g_Bph[m][rest] = pack_bf16x2(h0, h1);
        g_Bpl[m][rest] = pack_bf16x2(l0, l1);
    }
}

// ---------------- bf16x3 MMA GEMM body (R9-proven pipeline) -----------------
// C = act(A[M,128]) @ B[128,128]. 8 warps x 16 rows, k-chunk 16.
// MODE 0: A=x -> g_h (fp32). MODE 1: A=g_h + BN1 affine + ReLU -> g_hch (fp16).
#define APST 12
#define BPST 136
template <int MODE>
__device__ __forceinline__ void gemm_body(const float* __restrict__ Ain, int M, int blk) {
    __shared__ __align__(16) uint32_t Ahp[2][128 * APST], Alp[2][128 * APST];
    __shared__ __align__(16) uint32_t Bhp[2][8 * BPST],   Blp[2][8 * BPST];
    const float* A = (MODE == 0) ? Ain : g_h;

    const int tid  = threadIdx.x;
    const int w    = tid >> 5;
    const int lane = tid & 31;
    const int g    = lane >> 2;
    const int t    = lane & 3;
    const int row0 = blk * 128;

    const int r0_ = tid >> 2,         c40 = tid & 3;
    const int r1_ = (tid + 256) >> 2, c41 = (tid + 256) & 3;
    const int gr0 = row0 + r0_, gr1 = row0 + r1_;

    float acc[16][4];
    #pragma unroll
    for (int n = 0; n < 16; n++)
        #pragma unroll
        for (int i = 0; i < 4; i++) acc[n][i] = 0.f;

    auto loadA = [&](int kk, float4& v0, float4& v1) {
        v0 = make_float4(0.f, 0.f, 0.f, 0.f);
        v1 = make_float4(0.f, 0.f, 0.f, 0.f);
        if (gr0 < M) v0 = *(const float4*)(A + (size_t)gr0 * D + kk + c40 * 4);
        if (gr1 < M) v1 = *(const float4*)(A + (size_t)gr1 * D + kk + c41 * 4);
    };
    auto convertA = [&](int kk, int buf, float4 v0, float4 v1) {
        #pragma unroll
        for (int i = 0; i < 2; i++) {
            float4 v = i ? v1 : v0;
            int r = i ? r1_ : r0_;
            int c4 = i ? c41 : c40;
            if (MODE == 1) {
                int c = kk + c4 * 4;
                v.x = fmaxf(fmaf(v.x, g_a1[c + 0], g_c1[c + 0]), 0.f);
                v.y = fmaxf(fmaf(v.y, g_a1[c + 1], g_c1[c + 1]), 0.f);
                v.z = fmaxf(fmaf(v.z, g_a1[c + 2], g_c1[c + 2]), 0.f);
                v.w = fmaxf(fmaf(v.w, g_a1[c + 3], g_c1[c + 3]), 0.f);
            }
            float hx, lx, hy, ly, hz, lz, hw, lw;
            split_bf16(v.x, hx, lx); split_bf16(v.y, hy, ly);
            split_bf16(v.z, hz, lz); split_bf16(v.w, hw, lw);
            uint32_t* ph = &Ahp[buf][r * APST + c4 * 2];
            uint32_t* pl = &Alp[buf][r * APST + c4 * 2];
            ph[0] = pack_bf16x2(hx, hy); ph[1] = pack_bf16x2(hz, hw);
            pl[0] = pack_bf16x2(lx, ly); pl[1] = pack_bf16x2(lz, lw);
        }
    };
    auto issueB = [&](int c, int buf) {
        int k2l = tid >> 5, c4 = tid & 31;
        int srcw = (c * 8 + k2l) * D + c4 * 4;
        uint32_t dh = (uint32_t)__cvta_generic_to_shared(&Bhp[buf][k2l * BPST + c4 * 4]);
        uint32_t dl = (uint32_t)__cvta_generic_to_shared(&Blp[buf][k2l * BPST + c4 * 4]);
        asm volatile("cp.async.cg.shared.global [%0], [%1], 16;\n"
                     :: "r"(dh), "l"(&g_Bph[MODE][srcw]));
        asm volatile("cp.async.cg.shared.global [%0], [%1], 16;\n"
                     :: "r"(dl), "l"(&g_Bpl[MODE][srcw]));
        asm volatile("cp.async.commit_group;\n");
    };

    {
        float4 v0, v1;
        loadA(0, v0, v1);
        issueB(0, 0);
        convertA(0, 0, v0, v1);
        asm volatile("cp.async.wait_group 0;\n");
    }
    __syncthreads();

    for (int c = 0; c < 8; c++) {
        const int buf = c & 1, nb = buf ^ 1;
        const int kk = c * 16;
        float4 v0, v1;
        if (c < 7) {
            loadA(kk + 16, v0, v1);
            issueB(c + 1, nb);
        }

        uint32_t ah[4], al[4];
        {
            int ra = (w * 16 + g) * APST + t;
            int rb = (w * 16 + g + 8) * APST + t;
            ah[0] = Ahp[buf][ra];     ah[1] = Ahp[buf][rb];
            ah[2] = Ahp[buf][ra + 4]; ah[3] = Ahp[buf][rb + 4];
            al[0] = Alp[buf][ra];     al[1] = Alp[buf][rb];
            al[2] = Alp[buf][ra + 4]; al[3] = Alp[buf][rb + 4];
        }
        #pragma unroll
        for (int nt = 0; nt < 16; nt++) {
            int bi = t * BPST + nt * 8 + g;
            uint32_t bh0 = Bhp[buf][bi], bh1 = Bhp[buf][bi + 4 * BPST];
            uint32_t bl0 = Blp[buf][bi], bl1 = Blp[buf][bi + 4 * BPST];
            mma_bf16(acc[nt], ah, bh0, bh1);
            mma_bf16(acc[nt], ah, bl0, bl1);
            mma_bf16(acc[nt], al, bh0, bh1);
        }

        if (c < 7) {
            convertA(kk + 16, nb, v0, v1);
            asm volatile("cp.async.wait_group 0;\n");
            __syncthreads();
        }
    }

    int rA = row0 + w * 16 + g;
    int rB = rA + 8;
    #pragma unroll
    for (int nt = 0; nt < 16; nt++) {
        int col = nt * 8 + 2 * t;
        if (MODE == 0) {
            if (rA < M)
                *(float2*)(g_h + (size_t)rA * D + col) = make_float2(acc[nt][0], acc[nt][1]);
            if (rB < M)
                *(float2*)(g_h + (size_t)rB * D + col) = make_float2(acc[nt][2], acc[nt][3]);
        } else {
            if (rA < M)
                *(__half2*)(g_hch + (size_t)rA * D + col) =
                    __floats2half2_rn(acc[nt][0], acc[nt][1]);
            if (rB < M)
                *(__half2*)(g_hch + (size_t)rB * D + col) =
                    __floats2half2_rn(acc[nt][2], acc[nt][3]);
        }
    }
}

// ---------------- colstats body (which=0/1, + fused affine in last block) ---
__device__ __forceinline__ void colstats_body(int M, int which, int blk, int nblk,
                                              const float* __restrict__ gamma,
                                              const float* __restrict__ beta, float invN) {
    const float* X = (which == 0) ? g_h : g_acc;
    float* sum = (which == 0) ? g_sum1 : g_sum2;
    float* sq  = (which == 0) ? g_sq1  : g_sq2;
    __shared__ __align__(16) float ss[8][D], sr[8][D];
    __shared__ int lastblk;
    int tid = threadIdx.x;
    int wid = tid >> 5, lane = tid & 31;
    float4 s = make_float4(0.f, 0.f, 0.f, 0.f);
    float4 q = make_float4(0.f, 0.f, 0.f, 0.f);
    for (int r = blk * 8 + wid; r < M; r += nblk * 8) {
        float4 v = ((const float4*)(X + (size_t)r * D))[lane];
        s.x += v.x; s.y += v.y; s.z += v.z; s.w += v.w;
        q.x += v.x * v.x; q.y += v.y * v.y; q.z += v.z * v.z; q.w += v.w * v.w;
    }
    ((float4*)ss[wid])[lane] = s;
    ((float4*)sr[wid])[lane] = q;
    __syncthreads();
    if (tid < D) {
        float a = 0.f, b = 0.f;
        #pragma unroll
        for (int wv = 0; wv < 8; wv++) { a += ss[wv][tid]; b += sr[wv][tid]; }
        atomicAdd(&sum[tid], a);
        atomicAdd(&sq[tid], b);
    }
    __threadfence();
    __syncthreads();
    if (tid == 0) {
        int ret = atomicAdd(&g_ctr[which], 1);
        lastblk = (ret == nblk - 1);
    }
    __syncthreads();
    if (lastblk && tid < D) {
        float* a = (which == 0) ? g_a1 : g_a2;
        float* c = (which == 0) ? g_c1 : g_c2;
        float mean = __ldcg(&sum[tid]) * invN;
        float var  = __ldcg(&sq[tid]) * invN - mean * mean;
        float sc = gamma[tid] * rsqrtf(var + BN_EPS);
        a[tid] = sc;
        c[tid] = beta[tid] - mean * sc;
    }
}

// ---------------- merged kernel 2: gemm0 + degree histogram -----------------
__global__ void __launch_bounds__(256, 2) k_g0(const float* __restrict__ x,
                                               const int* __restrict__ dst,
                                               int E, int N, int GB) {
    if ((int)blockIdx.x < GB) {
        gemm_body<0>(x, N, blockIdx.x);
    } else {
        int e = (blockIdx.x - GB) * 256 + threadIdx.x;
        if (e < E) {
            int d = dst[e];
            if ((unsigned)d < (unsigned)N) atomicAdd(&g_degi[d], 1);
        }
    }
}

// ---------------- merged kernel 3: colstats0 + scan1 (phase2 in last block) -
__global__ void k_cs0s1(int N, const float* __restrict__ gam1,
                        const float* __restrict__ bet1, float invN, int nchunks) {
    if (blockIdx.x < 256) {
        colstats_body(N, 0, blockIdx.x, 256, gam1, bet1, invN);
        return;
    }
    // ---- scan1: per-chunk degree sums (256 thr, 2 elems each) ----
    __shared__ int red[256];
    __shared__ int lastblk1;
    int chunk = blockIdx.x - 256;
    int tid = threadIdx.x;
    int i0 = chunk * 512 + 2 * tid;
    int d0 = (i0 < N) ? g_degi[i0] : 0;
    int d1 = (i0 + 1 < N) ? g_degi[i0 + 1] : 0;
    red[tid] = d0 + d1;
    __syncthreads();
    #pragma unroll
    for (int off = 128; off > 0; off >>= 1) {
        if (tid < off) red[tid] += red[tid + off];
        __syncthreads();
    }
    if (tid == 0) g_part[chunk] = red[0];
    __threadfence();
    __syncthreads();
    if (tid == 0) {
        int ret = atomicAdd(&g_ctr[2], 1);
        lastblk1 = (ret == nchunks - 1);
    }
    __syncthreads();
    if (!lastblk1) return;

    __shared__ int s[MAXCHUNKS];
    if (tid < MAXCHUNKS)
        s[tid] = (tid < nchunks) ? __ldcg(&g_part[tid]) : 0;
    __syncthreads();
    #pragma unroll
    for (int off = 1; off < MAXCHUNKS; off <<= 1) {
        int v = 0, u = 0;
        if (tid < MAXCHUNKS) { v = s[tid]; u = (tid >= off) ? s[tid - off] : 0; }
        __syncthreads();
        if (tid < MAXCHUNKS) s[tid] = v + u;
        __syncthreads();
    }
    if (tid < nchunks) g_pbase[tid] = (tid > 0) ? s[tid - 1] : 0;
}

// ---------------- merged kernel 4: gemm1 + scan3 ----------------------------
__global__ void __launch_bounds__(256, 2) k_g1s3(int N, int GB) {
    if ((int)blockIdx.x < GB) {
        gemm_body<1>(nullptr, N, blockIdx.x);
        return;
    }
    // ---- scan3: intra-chunk exclusive scan + dinv (256 thr, pair scan) ----
    __shared__ int sp[256];
    int chunk = blockIdx.x - GB;
    int tid = threadIdx.x;
    int i0 = chunk * 512 + 2 * tid;
    int d0 = (i0 < N) ? g_degi[i0] : 0;
    int d1 = (i0 + 1 < N) ? g_degi[i0 + 1] : 0;
    int ps = d0 + d1;
    sp[tid] = ps;
    __syncthreads();
    #pragma unroll
    for (int off = 1; off < 256; off <<= 1) {
        int v = sp[tid];
        int u = (tid >= off) ? sp[tid - off] : 0;
        __syncthreads();
        sp[tid] = v + u;
        __syncthreads();
    }
    int base = g_pbase[chunk];
    int excl = base + sp[tid] - ps;
    if (i0 < N) {
        g_coff[i0] = excl;
        g_cursor[i0] = excl;
        g_dinv[i0] = rsqrtf((float)d0 + 1.0f);
        if (i0 == N - 1) g_coff[N] = excl + d0;
    }
    if (i0 + 1 < N) {
        g_coff[i0 + 1] = excl + d0;
        g_cursor[i0 + 1] = excl + d0;
        g_dinv[i0 + 1] = rsqrtf((float)d1 + 1.0f);
        if (i0 + 1 == N - 1) g_coff[N] = excl + d0 + d1;
    }
}

// ---------------- CSR fill ----------------
__global__ void k_fill(const int* __restrict__ src,
                       const int* __restrict__ dst, int E, int N) {
    int e = blockIdx.x * blockDim.x + threadIdx.x;
    if (e < E) {
        int d = dst[e], s = src[e];
        if ((unsigned)d < (unsigned)N && (unsigned)s < (unsigned)N) {
            int pos = atomicAdd(&g_cursor[d], 1);
            g_csr[pos] = s;
        }
    }
}

// ---------------- standalone colstats (which=1) ----------------
__global__ void k_colstats(int M, int which,
                           const float* __restrict__ gamma,
                           const float* __restrict__ beta, float invN) {
    colstats_body(M, which, blockIdx.x, gridDim.x, gamma, beta, invN);
}

// ---------------- gather aggregation (fp16 rows): warp per destination ------
__global__ void k_gather(int N) {
    int w = (blockIdx.x * blockDim.x + threadIdx.x) >> 5;
    int lane = threadIdx.x & 31;
    if (w >= N) return;
    int d = w;
    int beg = g_coff[d], end = g_coff[d + 1];
    float wd = g_dinv[d];

    auto loadrow = [&](int row, float2& f0, float2& f1) {
        uint2 raw = *(const uint2*)(g_hch + (size_t)row * D + lane * 4);
        f0 = __half22float2(*(__half2*)&raw.x);
        f1 = __half22float2(*(__half2*)&raw.y);
    };

    // self loop
    float2 f0, f1;
    loadrow(d, f0, f1);
    float w0 = wd * wd;
    float4 acc = make_float4(w0 * f0.x, w0 * f0.y, w0 * f1.x, w0 * f1.y);

    for (int j = beg; j < end; j += 32) {
        int myidx = 0;
        float myw = 0.f;
        if (j + lane < end) {
            myidx = g_csr[j + lane];
            myw = g_dinv[myidx] * wd;
        }
        int cnt = min(32, end - j);
        int t = 0;
        for (; t + 1 < cnt; t += 2) {   // 2-way MLP on neighbor rows
            int s0    = __shfl_sync(0xffffffffu, myidx, t);
            float ww0 = __shfl_sync(0xffffffffu, myw, t);
            int s1    = __shfl_sync(0xffffffffu, myidx, t + 1);
            float ww1 = __shfl_sync(0xffffffffu, myw, t + 1);
            float2 a0, a1, b0, b1;
            loadrow(s0, a0, a1);
            loadrow(s1, b0, b1);
            acc.x = fmaf(ww0, a0.x, acc.x); acc.y = fmaf(ww0, a0.y, acc.y);
            acc.z = fmaf(ww0, a1.x, acc.z); acc.w = fmaf(ww0, a1.y, acc.w);
            acc.x = fmaf(ww1, b0.x, acc.x); acc.y = fmaf(ww1, b0.y, acc.y);
            acc.z = fmaf(ww1, b1.x, acc.z); acc.w = fmaf(ww1, b1.y, acc.w);
        }
        if (t < cnt) {
            int s0    = __shfl_sync(0xffffffffu, myidx, t);
            float ww0 = __shfl_sync(0xffffffffu, myw, t);
            float2 a0, a1;
            loadrow(s0, a0, a1);
            acc.x = fmaf(ww0, a0.x, acc.x); acc.y = fmaf(ww0, a0.y, acc.y);
            acc.z = fmaf(ww0, a1.x, acc.z); acc.w = fmaf(ww0, a1.y, acc.w);
        }
    }
    ((float4*)(g_acc + (size_t)d * D))[lane] = acc;
}

// ---------------- finalize: BN2 affine + relu; reset ALL cross-call state ---
__global__ void k_final(float* __restrict__ out, int N) {
    int tt = blockIdx.x * blockDim.x + threadIdx.x;
    int r = tt >> 5, lane = tt & 31;
    if (blockIdx.x == 0) {
        if (threadIdx.x < 4) g_ctr[threadIdx.x] = 0;
        if (threadIdx.x < D) {      // reset BN stat accumulators for next replay
            g_sum1[threadIdx.x] = 0.f; g_sq1[threadIdx.x] = 0.f;
            g_sum2[threadIdx.x] = 0.f; g_sq2[threadIdx.x] = 0.f;
        }
    }
    if (r >= N) return;
    if (lane == 0) g_degi[r] = 0;
    float4 v = ((const float4*)(g_acc + (size_t)r * D))[lane];
    int c = lane * 4;
    v.x = fmaxf(fmaf(v.x, g_a2[c + 0], g_c2[c + 0]), 0.f);
    v.y = fmaxf(fmaf(v.y, g_a2[c + 1], g_c2[c + 1]), 0.f);
    v.z = fmaxf(fmaf(v.z, g_a2[c + 2], g_c2[c + 2]), 0.f);
    v.w = fmaxf(fmaf(v.w, g_a2[c + 3], g_c2[c + 3]), 0.f);
    ((float4*)(out + (size_t)r * D))[lane] = v;
}

// ---------------- launch ----------------
extern "C" void kernel_launch(void* const* d_in, const int* in_sizes, int n_in,
                              void* d_out, int out_size) {
    const float* x    = (const float*)d_in[0];
    const int*   ei   = (const int*)d_in[1];   // int64 in reference -> delivered int32
    const float* Wm   = (const float*)d_in[2];
    // d_in[3] = b_mlp  : cancels inside training-mode BatchNorm
    const float* gam1 = (const float*)d_in[4];
    const float* bet1 = (const float*)d_in[5];
    const float* Wc   = (const float*)d_in[6];
    // d_in[7] = b_conv : cancels inside training-mode BatchNorm
    const float* gam2 = (const float*)d_in[8];
    const float* bet2 = (const float*)d_in[9];
    float* out = (float*)d_out;

    const int N = in_sizes[0] / D;
    const int E = in_sizes[1] / 2;
    const int* srcp = ei;
    const int* dstp = ei + E;
    const float invN = 1.0f / (float)N;
    const int nchunks = (N + 511) / 512;
    const int EB = (E + 255) / 256;
    const int GB = (N + 127) / 128;

    k_pack<<<64, 256>>>(Wm, Wc);
    k_g0<<<GB + EB, 256>>>(x, dstp, E, N, GB);            // gemm0 + deg
    k_cs0s1<<<256 + nchunks, 256>>>(N, gam1, bet1, invN, nchunks);  // colstats0 + scan1/2
    k_g1s3<<<GB + nchunks, 256>>>(N, GB);                 // gemm1 + scan3
    k_fill<<<(E + 255) / 256, 256>>>(srcp, dstp, E, N);
    k_gather<<<(N * 32 + 255) / 256, 256>>>(N);
    k_colstats<<<256, 256>>>(N, 1, gam2, bet2, invN);
    k_final<<<(N * 32 + 255) / 256, 256>>>(out, N);
}